// round 1
// baseline (speedup 1.0000x reference)
#include <cuda_runtime.h>
#include <cuda_bf16.h>
#include <mma.h>

using namespace nvcuda;

// Problem dims (fixed by setup_inputs)
constexpr int NB = 512;   // batch B
constexpr int ND = 768;   // D
constexpr int NH = 256;   // H
constexpr int NQ = 128;   // n = B/4
constexpr int NM = 256;   // m = B/2
constexpr float TAU_INV = 2.0f;          // 1/tau
constexpr float PCOUNT = 57280.0f;       // number of en pairs

// ---------------- scratch (device globals; no allocation allowed) ----------
__device__ float g_z[NB * ND];                    // normalized embeddings
__device__ float g_A[NQ * NH];                    // z[:128] @ W1a^T
__device__ float g_Bf[NB * NH];                   // z @ W1b^T
__device__ __nv_bfloat16 g_W2h[NH * NH];          // W2 in bf16
__device__ float g_denomp[NQ * 4];                // per (i, kchunk) exp-sum partials
__device__ float g_pairp[NQ * 4];                 // per (i, kchunk) pair S sums
__device__ float g_bcep[1024];                    // per pair-block BCE partials

// ---------------- 1. row L2 normalize ----------------
__global__ void k_norm(const float* __restrict__ x) {
    int r = blockIdx.x;
    const float* xr = x + r * ND;
    float s = 0.f;
    for (int d = threadIdx.x; d < ND; d += 256) { float v = xr[d]; s += v * v; }
    __shared__ float sm[256];
    sm[threadIdx.x] = s;
    __syncthreads();
    for (int st = 128; st > 0; st >>= 1) {
        if (threadIdx.x < st) sm[threadIdx.x] += sm[threadIdx.x + st];
        __syncthreads();
    }
    float inv = 1.0f / fmaxf(sqrtf(sm[0]), 1e-12f);
    for (int d = threadIdx.x; d < ND; d += 256) g_z[r * ND + d] = xr[d] * inv;
}

// ---------------- 2. A = z[:128] @ W1[:, :768]^T ; Bf = z @ W1[:, 768:]^T ---
// blocks 0..15  : A rows  blockIdx.x*8 .. +8
// blocks 16..79 : Bf rows (blockIdx.x-16)*8 .. +8
__global__ void k_feat(const float* __restrict__ W1) {
    const int R = 8;
    int bx = blockIdx.x;
    bool isA = bx < 16;
    int rbase = isA ? bx * R : (bx - 16) * R;
    int off = isA ? 0 : ND;
    float* out = isA ? g_A : g_Bf;

    __shared__ float zs[R][ND];
    for (int idx = threadIdx.x; idx < R * ND; idx += 256)
        zs[idx / ND][idx % ND] = g_z[(rbase + idx / ND) * ND + (idx % ND)];
    __syncthreads();

    int h = threadIdx.x;  // 256 threads = 256 output features
    float acc[R];
#pragma unroll
    for (int r = 0; r < R; r++) acc[r] = 0.f;
    const float* wrow = W1 + h * (2 * ND) + off;
    for (int d = 0; d < ND; d += 4) {
        float4 w4 = *reinterpret_cast<const float4*>(wrow + d);
#pragma unroll
        for (int r = 0; r < R; r++) {
            acc[r] += zs[r][d] * w4.x + zs[r][d + 1] * w4.y
                    + zs[r][d + 2] * w4.z + zs[r][d + 3] * w4.w;
        }
    }
#pragma unroll
    for (int r = 0; r < R; r++) out[(rbase + r) * NH + h] = acc[r];
}

// ---------------- 3. W2 -> bf16 ----------------
__global__ void k_w2conv(const float* __restrict__ W2) {
    int t = blockIdx.x * 256 + threadIdx.x;
    if (t < NH * NH) g_W2h[t] = __float2bfloat16(W2[t]);
}

// ---------------- 4. contrastive partials ----------------
// grid (32, 4): block = (4 i's, 128-k chunk). Deterministic partials.
__global__ void k_contrast() {
    int ibase = blockIdx.x * 4;
    int kbase = blockIdx.y * 128;
    __shared__ float zi[4][ND];
    __shared__ float dsh[8][4], psh[8][4];
    for (int idx = threadIdx.x; idx < 4 * ND; idx += 256)
        zi[idx / ND][idx % ND] = g_z[(ibase + idx / ND) * ND + (idx % ND)];
    __syncthreads();

    int w = threadIdx.x >> 5, lane = threadIdx.x & 31;
    float dW[4] = {0.f, 0.f, 0.f, 0.f};
    float pW[4] = {0.f, 0.f, 0.f, 0.f};

    for (int kk = w; kk < 128; kk += 8) {
        int k = kbase + kk;
        const float* zk = g_z + k * ND;
        float s0 = 0.f, s1 = 0.f, s2 = 0.f, s3 = 0.f;
        for (int d = lane; d < ND; d += 32) {
            float v = zk[d];
            s0 += zi[0][d] * v; s1 += zi[1][d] * v;
            s2 += zi[2][d] * v; s3 += zi[3][d] * v;
        }
#pragma unroll
        for (int o = 16; o; o >>= 1) {
            s0 += __shfl_down_sync(0xffffffffu, s0, o);
            s1 += __shfl_down_sync(0xffffffffu, s1, o);
            s2 += __shfl_down_sync(0xffffffffu, s2, o);
            s3 += __shfl_down_sync(0xffffffffu, s3, o);
        }
        if (lane == 0) {
            float ss[4] = {s0, s1, s2, s3};
#pragma unroll
            for (int ii = 0; ii < 4; ii++) {
                int i = ibase + ii;
                if (k != i) dW[ii] += expf(TAU_INV * ss[ii]);
                if (k > i && k < NQ) pW[ii] += ss[ii];
            }
        }
    }
    if (lane == 0) {
#pragma unroll
        for (int ii = 0; ii < 4; ii++) { dsh[w][ii] = dW[ii]; psh[w][ii] = pW[ii]; }
    }
    __syncthreads();
    if (threadIdx.x < 4) {
        float d = 0.f, p = 0.f;
        for (int wv = 0; wv < 8; wv++) { d += dsh[wv][threadIdx.x]; p += psh[wv][threadIdx.x]; }
        g_denomp[(ibase + threadIdx.x) * 4 + blockIdx.y] = d;
        g_pairp[(ibase + threadIdx.x) * 4 + blockIdx.y] = p;
    }
}

// ---------------- 5. fused pair MLP (bf16 wmma) ----------------
// grid (128, 8): block = (i, 64 j's). h1 built in smem (bf16), GEMM vs W2,
// +b2, relu, dot w3, BCE for valid pairs (j > i), block partial out.
constexpr int LDH = 272;  // bf16 elems, 544B rows: 32B aligned, conflict-padded
__global__ void k_pair(const float* __restrict__ b1, const float* __restrict__ b2,
                       const float* __restrict__ w3, const float* __restrict__ b3v) {
    const int i = blockIdx.x;
    const int j0 = blockIdx.y * 64;

    __shared__ __align__(32) __nv_bfloat16 h1s[64 * LDH];
    __shared__ __align__(32) float cscr[8][256];
    __shared__ float lg2[2][64];
    __shared__ float red[64];

    // phase 1: h1 = relu(A[i] + Bf[j] + b1), bf16
    const float* Ai = g_A + i * NH;
    {
        int h = threadIdx.x;
        float ah = Ai[h] + b1[h];
#pragma unroll 4
        for (int p = 0; p < 64; p++) {
            float v = ah + g_Bf[(j0 + p) * NH + h];
            h1s[p * LDH + h] = __float2bfloat16(fmaxf(v, 0.f));
        }
    }
    __syncthreads();

    // phase 2: h2 = h1 @ W2^T via wmma; fold relu + dot(w3)
    int w = threadIdx.x >> 5, lane = threadIdx.x & 31;
    int pt = w & 3;        // p tile (16 rows)
    int oh = w >> 1 & 0;   // placeholder (computed below)
    oh = w >> 2;           // o half: warps 0-3 -> o[0,128), 4-7 -> o[128,256)
    int plocal = lane & 15, half = lane >> 4;
    float accL = 0.f;

    for (int ot = 0; ot < 8; ot++) {
        int obase = (oh * 8 + ot) * 16;
        wmma::fragment<wmma::accumulator, 16, 16, 16, float> cf;
        wmma::fill_fragment(cf, 0.f);
#pragma unroll
        for (int k = 0; k < 16; k++) {
            wmma::fragment<wmma::matrix_a, 16, 16, 16, __nv_bfloat16, wmma::row_major> af;
            wmma::fragment<wmma::matrix_b, 16, 16, 16, __nv_bfloat16, wmma::col_major> bf;
            wmma::load_matrix_sync(af, h1s + pt * 16 * LDH + k * 16, LDH);
            wmma::load_matrix_sync(bf, g_W2h + obase * NH + k * 16, NH);
            wmma::mma_sync(cf, af, bf, cf);
        }
        wmma::store_matrix_sync(cscr[w], cf, 16, wmma::mem_row_major);
        __syncwarp();
        const float* cs = cscr[w] + plocal * 16 + half * 8;
        const float* w3p = w3 + obase + half * 8;
        const float* b2p = b2 + obase + half * 8;
        float s = 0.f;
#pragma unroll
        for (int q = 0; q < 8; q++) s += fmaxf(cs[q] + b2p[q], 0.f) * w3p[q];
        accL += s;
        __syncwarp();
    }
    accL += __shfl_xor_sync(0xffffffffu, accL, 16);
    if (half == 0) lg2[oh][pt * 16 + plocal] = accL;
    __syncthreads();

    // phase 3: BCE for valid pairs, block reduce
    float bce = 0.f;
    if (threadIdx.x < 64) {
        int p = threadIdx.x;
        int j = j0 + p;
        if (j > i) {
            float logit = lg2[0][p] + lg2[1][p] + b3v[0];
            float lab = (j < NM) ? 1.f : 0.f;
            bce = fmaxf(logit, 0.f) - logit * lab + log1pf(expf(-fabsf(logit)));
        }
        red[p] = bce;
    }
    __syncthreads();
    if (threadIdx.x < 32) {
        float v = red[threadIdx.x] + red[threadIdx.x + 32];
#pragma unroll
        for (int o = 16; o; o >>= 1) v += __shfl_down_sync(0xffffffffu, v, o);
        if (threadIdx.x == 0) g_bcep[blockIdx.y * 128 + blockIdx.x] = v;
    }
}

// ---------------- 6. deterministic final reduce ----------------
__global__ void k_final(float* __restrict__ out) {
    __shared__ float s1[256];
    float b = 0.f;
    for (int t = threadIdx.x; t < 1024; t += 256) b += g_bcep[t];
    s1[threadIdx.x] = b;
    __syncthreads();
    for (int st = 128; st > 0; st >>= 1) {
        if (threadIdx.x < st) s1[threadIdx.x] += s1[threadIdx.x + st];
        __syncthreads();
    }
    float bsum = s1[0];
    __syncthreads();

    float c = 0.f;
    if (threadIdx.x < NQ) {
        int i = threadIdx.x;
        float den = g_denomp[i * 4 + 0] + g_denomp[i * 4 + 1]
                  + g_denomp[i * 4 + 2] + g_denomp[i * 4 + 3];
        float pr = g_pairp[i * 4 + 0] + g_pairp[i * 4 + 1]
                 + g_pairp[i * 4 + 2] + g_pairp[i * 4 + 3];
        c = (float)(NQ - 1 - i) * logf(den) - TAU_INV * pr;
    }
    s1[threadIdx.x] = c;
    __syncthreads();
    for (int st = 128; st > 0; st >>= 1) {
        if (threadIdx.x < st) s1[threadIdx.x] += s1[threadIdx.x + st];
        __syncthreads();
    }
    if (threadIdx.x == 0) {
        float closs = (-2.0f * (float)(NQ - 1) / (float)NQ) * s1[0];
        out[0] = closs + bsum / PCOUNT;
    }
}

// ---------------- launch ----------------
extern "C" void kernel_launch(void* const* d_in, const int* in_sizes, int n_in,
                              void* d_out, int out_size) {
    const float* emb = (const float*)d_in[0];
    const float* W1  = (const float*)d_in[1];
    const float* b1  = (const float*)d_in[2];
    const float* W2  = (const float*)d_in[3];
    const float* b2  = (const float*)d_in[4];
    const float* W3  = (const float*)d_in[5];
    const float* b3  = (const float*)d_in[6];

    k_norm<<<NB, 256>>>(emb);
    k_feat<<<80, 256>>>(W1);
    k_w2conv<<<NH * NH / 256, 256>>>(W2);
    k_contrast<<<dim3(32, 4), 256>>>();
    k_pair<<<dim3(NQ, 8), 256>>>(b1, b2, W3, b3);
    k_final<<<1, 256>>>((float*)d_out);
}

// round 2
// speedup vs baseline: 1.8197x; 1.8197x over previous
#include <cuda_runtime.h>
#include <cuda_bf16.h>
#include <mma.h>

using namespace nvcuda;

// Problem dims (fixed by setup_inputs)
constexpr int NB = 512;   // batch B
constexpr int ND = 768;   // D
constexpr int NH = 256;   // H
constexpr int NQ = 128;   // n = B/4
constexpr int NM = 256;   // m = B/2
constexpr float TAU_INV = 2.0f;          // 1/tau
constexpr float PCOUNT = 57280.0f;       // number of en pairs

// ---------------- scratch (device globals; no allocation allowed) ----------
__device__ float g_z[NB * ND];                    // normalized embeddings (fp32)
__device__ __nv_bfloat16 g_zh[NB * ND];           // normalized embeddings (bf16)
__device__ float g_A[NQ * NH];                    // z[:128] @ W1a^T
__device__ float g_Bf[NB * NH];                   // z @ W1b^T
__device__ __nv_bfloat16 g_W2h[NH * NH];          // W2 in bf16
__device__ float g_denomp[NQ * 4];                // per (i, kchunk) exp-sum partials
__device__ float g_pairp[NQ * 4];                 // per (i, kchunk) pair S sums
__device__ float g_bcep[1024];                    // per pair-block BCE partials

// ---------------- 1. row L2 normalize (fp32 + bf16 outputs) ----------------
__global__ void k_norm(const float* __restrict__ x) {
    int r = blockIdx.x;
    const float* xr = x + r * ND;
    float s = 0.f;
    for (int d = threadIdx.x; d < ND; d += 256) { float v = xr[d]; s += v * v; }
    __shared__ float sm[256];
    sm[threadIdx.x] = s;
    __syncthreads();
    for (int st = 128; st > 0; st >>= 1) {
        if (threadIdx.x < st) sm[threadIdx.x] += sm[threadIdx.x + st];
        __syncthreads();
    }
    float inv = 1.0f / fmaxf(sqrtf(sm[0]), 1e-12f);
    for (int d = threadIdx.x; d < ND; d += 256) {
        float v = xr[d] * inv;
        g_z[r * ND + d] = v;
        g_zh[r * ND + d] = __float2bfloat16(v);
    }
}

// ---------------- 2. A = z[:128] @ W1[:, :768]^T ; Bf = z @ W1[:, 768:]^T ---
__global__ void k_feat(const float* __restrict__ W1) {
    const int R = 8;
    int bx = blockIdx.x;
    bool isA = bx < 16;
    int rbase = isA ? bx * R : (bx - 16) * R;
    int off = isA ? 0 : ND;
    float* out = isA ? g_A : g_Bf;

    __shared__ float zs[R][ND];
    for (int idx = threadIdx.x; idx < R * ND; idx += 256)
        zs[idx / ND][idx % ND] = g_z[(rbase + idx / ND) * ND + (idx % ND)];
    __syncthreads();

    int h = threadIdx.x;
    float acc[R];
#pragma unroll
    for (int r = 0; r < R; r++) acc[r] = 0.f;
    const float* wrow = W1 + h * (2 * ND) + off;
    for (int d = 0; d < ND; d += 4) {
        float4 w4 = *reinterpret_cast<const float4*>(wrow + d);
#pragma unroll
        for (int r = 0; r < R; r++) {
            acc[r] += zs[r][d] * w4.x + zs[r][d + 1] * w4.y
                    + zs[r][d + 2] * w4.z + zs[r][d + 3] * w4.w;
        }
    }
#pragma unroll
    for (int r = 0; r < R; r++) out[(rbase + r) * NH + h] = acc[r];
}

// ---------------- 3. W2 -> bf16 ----------------
__global__ void k_w2conv(const float* __restrict__ W2) {
    int t = blockIdx.x * 256 + threadIdx.x;
    if (t < NH * NH) g_W2h[t] = __float2bfloat16(W2[t]);
}

// ---------------- 4. contrastive partials via wmma ----------------
// grid (8, 4): block = (16 i-rows, 128 k-cols). 8 warps, each a 16x16 S tile.
constexpr int LZA = 776;   // 768 + 8 bf16 pad
constexpr int LSS = 132;   // 128 + 4 fp32 pad
__global__ void k_contrast() {
    const int ibase = blockIdx.x * 16;
    const int kbase = blockIdx.y * 128;
    __shared__ __align__(16) __nv_bfloat16 za[16 * LZA];   // ~24.8KB
    __shared__ float Ssh[16 * LSS];                         // ~8.4KB

    // stage A tile (16 x 768 bf16), vectorized 16B copies
    for (int c = threadIdx.x; c < 16 * (ND / 8); c += 256) {
        int r = c / (ND / 8);
        int d8 = c % (ND / 8);
        *reinterpret_cast<uint4*>(za + r * LZA + d8 * 8) =
            *reinterpret_cast<const uint4*>(g_zh + (ibase + r) * ND + d8 * 8);
    }
    __syncthreads();

    int w = threadIdx.x >> 5, lane = threadIdx.x & 31;
    int kcol = w * 16;

    wmma::fragment<wmma::accumulator, 16, 16, 16, float> cf;
    wmma::fill_fragment(cf, 0.f);
    for (int kc = 0; kc < ND / 16; kc++) {
        wmma::fragment<wmma::matrix_a, 16, 16, 16, __nv_bfloat16, wmma::row_major> af;
        wmma::fragment<wmma::matrix_b, 16, 16, 16, __nv_bfloat16, wmma::col_major> bf;
        wmma::load_matrix_sync(af, za + kc * 16, LZA);
        wmma::load_matrix_sync(bf, g_zh + (kbase + kcol) * ND + kc * 16, ND);
        wmma::mma_sync(cf, af, bf, cf);
    }
    wmma::store_matrix_sync(Ssh + kcol, cf, LSS, wmma::mem_row_major);
    __syncthreads();

    // warp w reduces rows 2w, 2w+1 over 128 cols
#pragma unroll
    for (int rr = 2 * w; rr <= 2 * w + 1; rr++) {
        int i = ibase + rr;
        float dacc = 0.f, pacc = 0.f;
#pragma unroll
        for (int cc = 0; cc < 4; cc++) {
            int c = lane + cc * 32;
            int k = kbase + c;
            float s = Ssh[rr * LSS + c];
            if (k != i) dacc += expf(TAU_INV * s);
            if (blockIdx.y == 0 && k > i) pacc += s;   // k<128 implied by by==0
        }
#pragma unroll
        for (int o = 16; o; o >>= 1) {
            dacc += __shfl_down_sync(0xffffffffu, dacc, o);
            pacc += __shfl_down_sync(0xffffffffu, pacc, o);
        }
        if (lane == 0) {
            g_denomp[i * 4 + blockIdx.y] = dacc;
            g_pairp[i * 4 + blockIdx.y] = pacc;
        }
    }
}

// ---------------- 5. fused pair MLP (bf16 wmma, W2 staged in smem) ---------
// grid (128, 8): block = (i, 64 j's), 128 threads = 4 warps.
// Warp w owns rows [w*16, w*16+16); loops all 16 o-tiles with a shared W2 slab.
// The slab buffer is reused as C scratch after the mma reads for each o-tile.
constexpr int LDH = 264;   // h1s row stride (bf16), pad for conflict-free ldsm
constexpr int LDW = 264;   // w2 slab row stride (bf16)
__global__ void __launch_bounds__(128, 4)
k_pair(const float* __restrict__ b1, const float* __restrict__ b2,
       const float* __restrict__ w3, const float* __restrict__ b3v) {
    const int i = blockIdx.x;
    const int j0 = blockIdx.y * 64;

    __shared__ __align__(16) __nv_bfloat16 h1s[64 * LDH];   // 33.8KB
    __shared__ __align__(16) float wcscr[16 * LDW / 2];     // 8.4KB (slab / C union)
    __shared__ float lgrow[64];
    __shared__ float red[64];
    __nv_bfloat16* w2s = reinterpret_cast<__nv_bfloat16*>(wcscr);

    // phase 1: h1 = relu(A[i] + Bf[j] + b1), bf16, 64 rows x 256 cols
    const float* Ai = g_A + i * NH;
    {
        int h0 = threadIdx.x;          // covers h0 and h0+128
        float a0 = Ai[h0] + b1[h0];
        float a1 = Ai[h0 + 128] + b1[h0 + 128];
        for (int p = 0; p < 64; p++) {
            const float* bfr = g_Bf + (j0 + p) * NH;
            h1s[p * LDH + h0]       = __float2bfloat16(fmaxf(a0 + bfr[h0], 0.f));
            h1s[p * LDH + h0 + 128] = __float2bfloat16(fmaxf(a1 + bfr[h0 + 128], 0.f));
        }
    }
    __syncthreads();

    const int w = threadIdx.x >> 5, lane = threadIdx.x & 31;
    const int plocal = lane & 15, half = lane >> 4;
    float accL = 0.f;

    for (int ot = 0; ot < 16; ot++) {
        const int obase = ot * 16;
        // stage W2 slab: rows obase..obase+16 (16 x 256 bf16)
        for (int c = threadIdx.x; c < 16 * (NH / 8); c += 128) {
            int oo = c / (NH / 8);
            int k8 = c % (NH / 8);
            *reinterpret_cast<uint4*>(w2s + oo * LDW + k8 * 8) =
                *reinterpret_cast<const uint4*>(g_W2h + (obase + oo) * NH + k8 * 8);
        }
        __syncthreads();

        wmma::fragment<wmma::accumulator, 16, 16, 16, float> cf;
        wmma::fill_fragment(cf, 0.f);
#pragma unroll
        for (int k = 0; k < 16; k++) {
            wmma::fragment<wmma::matrix_a, 16, 16, 16, __nv_bfloat16, wmma::row_major> af;
            wmma::fragment<wmma::matrix_b, 16, 16, 16, __nv_bfloat16, wmma::col_major> bf;
            wmma::load_matrix_sync(af, h1s + w * 16 * LDH + k * 16, LDH);
            wmma::load_matrix_sync(bf, w2s + k * 16, LDW);
            wmma::mma_sync(cf, af, bf, cf);
        }
        __syncthreads();   // all warps done reading slab; safe to overwrite

        float* cs = wcscr + w * 256;
        wmma::store_matrix_sync(cs, cf, 16, wmma::mem_row_major);
        __syncwarp();
        const float* cp = cs + plocal * 16 + half * 8;
        const float* w3p = w3 + obase + half * 8;
        const float* b2p = b2 + obase + half * 8;
        float s = 0.f;
#pragma unroll
        for (int q = 0; q < 8; q++) s += fmaxf(cp[q] + b2p[q], 0.f) * w3p[q];
        accL += s;
        __syncthreads();   // epilogue reads done; next ot may restage slab
    }

    accL += __shfl_xor_sync(0xffffffffu, accL, 16);
    if (half == 0) lgrow[w * 16 + plocal] = accL;
    __syncthreads();

    // phase 3: BCE for valid pairs, block reduce
    float bce = 0.f;
    if (threadIdx.x < 64) {
        int p = threadIdx.x;
        int j = j0 + p;
        if (j > i) {
            float logit = lgrow[p] + b3v[0];
            float lab = (j < NM) ? 1.f : 0.f;
            bce = fmaxf(logit, 0.f) - logit * lab + log1pf(expf(-fabsf(logit)));
        }
        red[p] = bce;
    }
    __syncthreads();
    if (threadIdx.x < 32) {
        float v = red[threadIdx.x] + red[threadIdx.x + 32];
#pragma unroll
        for (int o = 16; o; o >>= 1) v += __shfl_down_sync(0xffffffffu, v, o);
        if (threadIdx.x == 0) g_bcep[blockIdx.y * 128 + blockIdx.x] = v;
    }
}

// ---------------- 6. deterministic final reduce ----------------
__global__ void k_final(float* __restrict__ out) {
    __shared__ float s1[256];
    float b = 0.f;
    for (int t = threadIdx.x; t < 1024; t += 256) b += g_bcep[t];
    s1[threadIdx.x] = b;
    __syncthreads();
    for (int st = 128; st > 0; st >>= 1) {
        if (threadIdx.x < st) s1[threadIdx.x] += s1[threadIdx.x + st];
        __syncthreads();
    }
    float bsum = s1[0];
    __syncthreads();

    float c = 0.f;
    if (threadIdx.x < NQ) {
        int i = threadIdx.x;
        float den = g_denomp[i * 4 + 0] + g_denomp[i * 4 + 1]
                  + g_denomp[i * 4 + 2] + g_denomp[i * 4 + 3];
        float pr = g_pairp[i * 4 + 0] + g_pairp[i * 4 + 1]
                 + g_pairp[i * 4 + 2] + g_pairp[i * 4 + 3];
        c = (float)(NQ - 1 - i) * logf(den) - TAU_INV * pr;
    }
    s1[threadIdx.x] = c;
    __syncthreads();
    for (int st = 128; st > 0; st >>= 1) {
        if (threadIdx.x < st) s1[threadIdx.x] += s1[threadIdx.x + st];
        __syncthreads();
    }
    if (threadIdx.x == 0) {
        float closs = (-2.0f * (float)(NQ - 1) / (float)NQ) * s1[0];
        out[0] = closs + bsum / PCOUNT;
    }
}

// ---------------- launch ----------------
extern "C" void kernel_launch(void* const* d_in, const int* in_sizes, int n_in,
                              void* d_out, int out_size) {
    const float* emb = (const float*)d_in[0];
    const float* W1  = (const float*)d_in[1];
    const float* b1  = (const float*)d_in[2];
    const float* W2  = (const float*)d_in[3];
    const float* b2  = (const float*)d_in[4];
    const float* W3  = (const float*)d_in[5];
    const float* b3  = (const float*)d_in[6];

    k_norm<<<NB, 256>>>(emb);
    k_feat<<<80, 256>>>(W1);
    k_w2conv<<<NH * NH / 256, 256>>>(W2);
    k_contrast<<<dim3(8, 4), 256>>>();
    k_pair<<<dim3(NQ, 8), 128>>>(b1, b2, W3, b3);
    k_final<<<1, 256>>>((float*)d_out);
}

// round 4
// speedup vs baseline: 2.6368x; 1.4490x over previous
#include <cuda_runtime.h>
#include <cuda_bf16.h>
#include <mma.h>
#include <cstdint>

using namespace nvcuda;

constexpr int NB = 512;   // batch B
constexpr int ND = 768;   // D
constexpr int NH = 256;   // H
constexpr int NQ = 128;   // n = B/4
constexpr int NM = 256;   // m = B/2
constexpr float TAU_INV = 2.0f;
constexpr float PCOUNT = 57280.0f;

// ---------------- scratch ----------------
__device__ float g_z[NB * ND];
__device__ __nv_bfloat16 g_zh[NB * ND];
__device__ __nv_bfloat16 g_W1h[NH * 2 * ND];
__device__ __nv_bfloat16 g_W2h[NH * NH];
__device__ float g_A[NQ * NH];
__device__ float g_Bf[NB * NH];
__device__ float g_denomp[NQ * 4];
__device__ float g_pairp[NQ * 4];
__device__ float g_bcep[512];

// ---------------- 1. row L2 normalize ----------------
__global__ void k_norm(const float* __restrict__ x) {
    int r = blockIdx.x;
    const float* xr = x + r * ND;
    float s = 0.f;
    for (int d = threadIdx.x; d < ND; d += 256) { float v = xr[d]; s += v * v; }
    __shared__ float sm[256];
    sm[threadIdx.x] = s;
    __syncthreads();
    for (int st = 128; st > 0; st >>= 1) {
        if (threadIdx.x < st) sm[threadIdx.x] += sm[threadIdx.x + st];
        __syncthreads();
    }
    float inv = 1.0f / fmaxf(sqrtf(sm[0]), 1e-12f);
    for (int d = threadIdx.x; d < ND; d += 256) {
        float v = xr[d] * inv;
        g_z[r * ND + d] = v;
        g_zh[r * ND + d] = __float2bfloat16(v);
    }
}

// ---------------- 2. convert W1 & W2 to bf16 ----------------
__global__ void k_conv(const float* __restrict__ W1, const float* __restrict__ W2) {
    int t = blockIdx.x * 256 + threadIdx.x;
    const int N1 = NH * 2 * ND;                // 393216
    if (t < N1) g_W1h[t] = __float2bfloat16(W1[t]);
    else {
        int u = t - N1;
        if (u < NH * NH) g_W2h[u] = __float2bfloat16(W2[u]);
    }
}

// ---------------- 3. feature GEMMs via wmma ----------------
// virtual row-tiles: t<8 -> A (z rows t*16, off 0); t>=8 -> Bf (z rows (t-8)*16, off 768)
constexpr int LZF = 776;
__global__ void __launch_bounds__(256, 1) k_featw() {
    const int t = blockIdx.x;
    const bool isA = t < 8;
    const int rbase = (isA ? t : t - 8) * 16;
    const int off = isA ? 0 : ND;
    float* out = (isA ? g_A : g_Bf) + rbase * NH;

    __shared__ __align__(16) __nv_bfloat16 za[16 * LZF];
    for (int c = threadIdx.x; c < 16 * (ND / 8); c += 256) {
        int r = c / (ND / 8), d8 = c % (ND / 8);
        *reinterpret_cast<uint4*>(za + r * LZF + d8 * 8) =
            *reinterpret_cast<const uint4*>(g_zh + (rbase + r) * ND + d8 * 8);
    }
    __syncthreads();

    int w = threadIdx.x >> 5;
    int h0 = w * 32, h1 = h0 + 16;
    wmma::fragment<wmma::accumulator, 16, 16, 16, float> cf0, cf1;
    wmma::fill_fragment(cf0, 0.f);
    wmma::fill_fragment(cf1, 0.f);
    for (int kc = 0; kc < ND / 16; kc++) {
        wmma::fragment<wmma::matrix_a, 16, 16, 16, __nv_bfloat16, wmma::row_major> af;
        wmma::fragment<wmma::matrix_b, 16, 16, 16, __nv_bfloat16, wmma::col_major> bf0, bf1;
        wmma::load_matrix_sync(af, za + kc * 16, LZF);
        wmma::load_matrix_sync(bf0, g_W1h + h0 * (2 * ND) + off + kc * 16, 2 * ND);
        wmma::load_matrix_sync(bf1, g_W1h + h1 * (2 * ND) + off + kc * 16, 2 * ND);
        wmma::mma_sync(cf0, af, bf0, cf0);
        wmma::mma_sync(cf1, af, bf1, cf1);
    }
    wmma::store_matrix_sync(out + h0, cf0, NH, wmma::mem_row_major);
    wmma::store_matrix_sync(out + h1, cf1, NH, wmma::mem_row_major);
}

// ---------------- 4. contrastive partials (smem-staged, dual acc) ---------
constexpr int LZA = 776;   // za row stride (bf16)
constexpr int LZB = 200;   // zb row stride (bf16), chunk width 192
constexpr int LSS = 132;   // S row stride (fp32)
constexpr int C_ZA = 0;
constexpr int C_ZB = 16 * LZA * 2;                 // 24832
constexpr int C_SS = C_ZB + 128 * LZB * 2;         // 76032
constexpr int C_SMEM = C_SS + 16 * LSS * 4;        // 84480
__global__ void __launch_bounds__(256, 1) k_contrast() {
    extern __shared__ __align__(16) char dyn[];
    __nv_bfloat16* za = reinterpret_cast<__nv_bfloat16*>(dyn + C_ZA);
    __nv_bfloat16* zb = reinterpret_cast<__nv_bfloat16*>(dyn + C_ZB);
    float* Ssh = reinterpret_cast<float*>(dyn + C_SS);

    const int ibase = blockIdx.x * 16;
    const int kbase = blockIdx.y * 128;

    for (int c = threadIdx.x; c < 16 * (ND / 8); c += 256) {
        int r = c / (ND / 8), d8 = c % (ND / 8);
        *reinterpret_cast<uint4*>(za + r * LZA + d8 * 8) =
            *reinterpret_cast<const uint4*>(g_zh + (ibase + r) * ND + d8 * 8);
    }

    int w = threadIdx.x >> 5, lane = threadIdx.x & 31;
    int kcol = w * 16;

    wmma::fragment<wmma::accumulator, 16, 16, 16, float> cf0, cf1;
    wmma::fill_fragment(cf0, 0.f);
    wmma::fill_fragment(cf1, 0.f);

    for (int ch = 0; ch < 4; ch++) {
        const int d0 = ch * 192;
        __syncthreads();   // prev chunk consumed (and za ready on ch==0)
        for (int c = threadIdx.x; c < 128 * (192 / 8); c += 256) {
            int kk = c / (192 / 8), d8 = c % (192 / 8);
            *reinterpret_cast<uint4*>(zb + kk * LZB + d8 * 8) =
                *reinterpret_cast<const uint4*>(g_zh + (kbase + kk) * ND + d0 + d8 * 8);
        }
        __syncthreads();
#pragma unroll
        for (int kc = 0; kc < 12; kc += 2) {
            wmma::fragment<wmma::matrix_a, 16, 16, 16, __nv_bfloat16, wmma::row_major> af0, af1;
            wmma::fragment<wmma::matrix_b, 16, 16, 16, __nv_bfloat16, wmma::col_major> bf0, bf1;
            wmma::load_matrix_sync(af0, za + (d0 + kc * 16), LZA);
            wmma::load_matrix_sync(bf0, zb + kcol * LZB + kc * 16, LZB);
            wmma::load_matrix_sync(af1, za + (d0 + (kc + 1) * 16), LZA);
            wmma::load_matrix_sync(bf1, zb + kcol * LZB + (kc + 1) * 16, LZB);
            wmma::mma_sync(cf0, af0, bf0, cf0);
            wmma::mma_sync(cf1, af1, bf1, cf1);
        }
    }
#pragma unroll
    for (int e = 0; e < cf0.num_elements; e++) cf0.x[e] += cf1.x[e];
    __syncthreads();
    wmma::store_matrix_sync(Ssh + kcol, cf0, LSS, wmma::mem_row_major);
    __syncthreads();

#pragma unroll
    for (int rr = 2 * w; rr <= 2 * w + 1; rr++) {
        int i = ibase + rr;
        float dacc = 0.f, pacc = 0.f;
#pragma unroll
        for (int cc = 0; cc < 4; cc++) {
            int c = lane + cc * 32;
            int k = kbase + c;
            float s = Ssh[rr * LSS + c];
            if (k != i) dacc += expf(TAU_INV * s);
            if (blockIdx.y == 0 && k > i) pacc += s;
        }
#pragma unroll
        for (int o = 16; o; o >>= 1) {
            dacc += __shfl_down_sync(0xffffffffu, dacc, o);
            pacc += __shfl_down_sync(0xffffffffu, pacc, o);
        }
        if (lane == 0) {
            g_denomp[i * 4 + blockIdx.y] = dacc;
            g_pairp[i * 4 + blockIdx.y] = pacc;
        }
    }
}

// ---------------- 5. fused pair MLP: W2 fully resident, no mainloop barriers
constexpr int LDH = 264;
constexpr int LDW = 264;
constexpr int P_H1 = 0;
constexpr int P_W2 = 128 * LDH * 2;                 // 67584
constexpr int P_CS = P_W2 + 256 * LDW * 2;          // 202752
constexpr int P_ASH = P_CS + 8 * 512 * 4;           // 219136
constexpr int P_B2S = P_ASH + 256 * 4;              // 220160
constexpr int P_W3S = P_B2S + 256 * 4;              // 221184
constexpr int P_RED = P_W3S + 256 * 4;              // 222208
constexpr int P_SMEM = P_RED + 128 * 4;             // 222720
__global__ void __launch_bounds__(256, 1)
k_pair(const float* __restrict__ b1, const float* __restrict__ b2,
       const float* __restrict__ w3, const float* __restrict__ b3v) {
    extern __shared__ __align__(16) char dyn[];
    __nv_bfloat16* h1s = reinterpret_cast<__nv_bfloat16*>(dyn + P_H1);
    __nv_bfloat16* w2s = reinterpret_cast<__nv_bfloat16*>(dyn + P_W2);
    float* cscr = reinterpret_cast<float*>(dyn + P_CS);
    float* ash  = reinterpret_cast<float*>(dyn + P_ASH);
    float* b2s  = reinterpret_cast<float*>(dyn + P_B2S);
    float* w3s  = reinterpret_cast<float*>(dyn + P_W3S);
    float* red  = reinterpret_cast<float*>(dyn + P_RED);

    const int i = blockIdx.x;
    const int j0 = blockIdx.y * 128;

    // stage biases / w3 / a-row
    {
        int h = threadIdx.x;
        ash[h] = g_A[i * NH + h] + b1[h];
        b2s[h] = b2[h];
        w3s[h] = w3[h];
    }
    // stage W2 (256 x 256 bf16)
    for (int c = threadIdx.x; c < 256 * 32; c += 256) {
        int oo = c >> 5, q = c & 31;
        *reinterpret_cast<uint4*>(w2s + oo * LDW + q * 8) =
            *reinterpret_cast<const uint4*>(g_W2h + oo * NH + q * 8);
    }
    __syncthreads();

    // h1 = relu(ash + Bf[j]) bf16, 128 rows x 256
    for (int c = threadIdx.x; c < 128 * 64; c += 256) {
        int j = c >> 6, q4 = c & 63;
        float4 bv = *reinterpret_cast<const float4*>(g_Bf + (j0 + j) * NH + q4 * 4);
        float4 av = *reinterpret_cast<const float4*>(ash + q4 * 4);
        __nv_bfloat162 pk2[2];
        pk2[0] = __floats2bfloat162_rn(fmaxf(av.x + bv.x, 0.f),
                                       fmaxf(av.y + bv.y, 0.f));
        pk2[1] = __floats2bfloat162_rn(fmaxf(av.z + bv.z, 0.f),
                                       fmaxf(av.w + bv.w, 0.f));
        *reinterpret_cast<__nv_bfloat162*>(h1s + j * LDH + q4 * 4) = pk2[0];
        *reinterpret_cast<__nv_bfloat162*>(h1s + j * LDH + q4 * 4 + 2) = pk2[1];
    }
    __syncthreads();

    const int w = threadIdx.x >> 5, lane = threadIdx.x & 31;
    const int plocal = lane & 15, half = lane >> 4;
    float* cs = cscr + w * 512;
    float accL = 0.f;

    for (int ot = 0; ot < 8; ot++) {
        const int o0 = ot * 16, o1 = o0 + 128;
        wmma::fragment<wmma::accumulator, 16, 16, 16, float> cf0, cf1;
        wmma::fill_fragment(cf0, 0.f);
        wmma::fill_fragment(cf1, 0.f);
#pragma unroll
        for (int k = 0; k < 16; k++) {
            wmma::fragment<wmma::matrix_a, 16, 16, 16, __nv_bfloat16, wmma::row_major> af;
            wmma::fragment<wmma::matrix_b, 16, 16, 16, __nv_bfloat16, wmma::col_major> bf0, bf1;
            wmma::load_matrix_sync(af, h1s + w * 16 * LDH + k * 16, LDH);
            wmma::load_matrix_sync(bf0, w2s + o0 * LDW + k * 16, LDW);
            wmma::load_matrix_sync(bf1, w2s + o1 * LDW + k * 16, LDW);
            wmma::mma_sync(cf0, af, bf0, cf0);
            wmma::mma_sync(cf1, af, bf1, cf1);
        }
        wmma::store_matrix_sync(cs, cf0, 16, wmma::mem_row_major);
        wmma::store_matrix_sync(cs + 256, cf1, 16, wmma::mem_row_major);
        __syncwarp();
        const float* cp0 = cs + plocal * 16 + half * 8;
        const float* cp1 = cp0 + 256;
        float s = 0.f;
#pragma unroll
        for (int q = 0; q < 8; q++) {
            int oa = o0 + half * 8 + q, ob = o1 + half * 8 + q;
            s += fmaxf(cp0[q] + b2s[oa], 0.f) * w3s[oa];
            s += fmaxf(cp1[q] + b2s[ob], 0.f) * w3s[ob];
        }
        accL += s;
        __syncwarp();
    }

    accL += __shfl_xor_sync(0xffffffffu, accL, 16);
    // reuse red[] for per-row logits then BCE
    if (half == 0) red[w * 16 + plocal] = accL;
    __syncthreads();

    float bce = 0.f;
    if (threadIdx.x < 128) {
        int j = j0 + threadIdx.x;
        if (j > i) {
            float logit = red[threadIdx.x] + b3v[0];
            float lab = (j < NM) ? 1.f : 0.f;
            bce = fmaxf(logit, 0.f) - logit * lab + log1pf(expf(-fabsf(logit)));
        }
    }
    __syncthreads();
    if (threadIdx.x < 128) red[threadIdx.x] = bce;
    __syncthreads();
    if (threadIdx.x < 32) {
        float v = red[threadIdx.x] + red[threadIdx.x + 32]
                + red[threadIdx.x + 64] + red[threadIdx.x + 96];
#pragma unroll
        for (int o = 16; o; o >>= 1) v += __shfl_down_sync(0xffffffffu, v, o);
        if (threadIdx.x == 0) g_bcep[blockIdx.y * 128 + blockIdx.x] = v;
    }
}

// ---------------- 6. final reduce ----------------
__global__ void k_final(float* __restrict__ out) {
    __shared__ float s1[256];
    float b = 0.f;
    for (int t = threadIdx.x; t < 512; t += 256) b += g_bcep[t];
    s1[threadIdx.x] = b;
    __syncthreads();
    for (int st = 128; st > 0; st >>= 1) {
        if (threadIdx.x < st) s1[threadIdx.x] += s1[threadIdx.x + st];
        __syncthreads();
    }
    float bsum = s1[0];
    __syncthreads();

    float c = 0.f;
    if (threadIdx.x < NQ) {
        int i = threadIdx.x;
        float den = g_denomp[i * 4 + 0] + g_denomp[i * 4 + 1]
                  + g_denomp[i * 4 + 2] + g_denomp[i * 4 + 3];
        float pr = g_pairp[i * 4 + 0] + g_pairp[i * 4 + 1]
                 + g_pairp[i * 4 + 2] + g_pairp[i * 4 + 3];
        c = (float)(NQ - 1 - i) * logf(den) - TAU_INV * pr;
    }
    s1[threadIdx.x] = c;
    __syncthreads();
    for (int st = 128; st > 0; st >>= 1) {
        if (threadIdx.x < st) s1[threadIdx.x] += s1[threadIdx.x + st];
        __syncthreads();
    }
    if (threadIdx.x == 0) {
        float closs = (-2.0f * (float)(NQ - 1) / (float)NQ) * s1[0];
        out[0] = closs + bsum / PCOUNT;
    }
}

// ---------------- launch ----------------
extern "C" void kernel_launch(void* const* d_in, const int* in_sizes, int n_in,
                              void* d_out, int out_size) {
    const float* emb = (const float*)d_in[0];
    const float* W1  = (const float*)d_in[1];
    const float* b1  = (const float*)d_in[2];
    const float* W2  = (const float*)d_in[3];
    const float* b2  = (const float*)d_in[4];
    const float* W3  = (const float*)d_in[5];
    const float* b3  = (const float*)d_in[6];

    cudaFuncSetAttribute(k_contrast, cudaFuncAttributeMaxDynamicSharedMemorySize, C_SMEM);
    cudaFuncSetAttribute(k_pair, cudaFuncAttributeMaxDynamicSharedMemorySize, P_SMEM);

    k_norm<<<NB, 256>>>(emb);
    k_conv<<<(NH * 2 * ND + NH * NH + 255) / 256, 256>>>(W1, W2);
    k_featw<<<40, 256>>>();
    k_contrast<<<dim3(8, 4), 256, C_SMEM>>>();
    k_pair<<<dim3(NQ, 4), 256, P_SMEM>>>(b1, b2, W3, b3);
    k_final<<<1, 256>>>((float*)d_out);
}

// round 5
// speedup vs baseline: 3.1525x; 1.1956x over previous
#include <cuda_runtime.h>
#include <cuda_bf16.h>
#include <mma.h>
#include <cstdint>

using namespace nvcuda;

constexpr int NB = 512;   // batch B
constexpr int ND = 768;   // D
constexpr int NH = 256;   // H
constexpr int NQ = 128;   // n = B/4
constexpr int NM = 256;   // m = B/2
constexpr float TAU_INV = 2.0f;
constexpr float PCOUNT = 57280.0f;

// ---------------- scratch ----------------
__device__ __nv_bfloat16 g_zh[NB * ND];
__device__ __nv_bfloat16 g_W1h[NH * 2 * ND];
__device__ __nv_bfloat16 g_W2h[NH * NH];
__device__ float g_A[NQ * NH];
__device__ float g_Bf[NB * NH];
__device__ float g_denomp[NQ * 8];
__device__ float g_pairp[NQ * 8];
__device__ float g_bcep[128];

// ================= kernel A: norm (bx<512) | W1/W2 bf16 convert ===========
__global__ void k_prep(const float* __restrict__ x,
                       const float* __restrict__ W1, const float* __restrict__ W2) {
    int bx = blockIdx.x;
    if (bx < NB) {
        const float* xr = x + bx * ND;
        float s = 0.f;
        for (int d = threadIdx.x; d < ND; d += 256) { float v = xr[d]; s += v * v; }
        __shared__ float sm[256];
        sm[threadIdx.x] = s;
        __syncthreads();
        for (int st = 128; st > 0; st >>= 1) {
            if (threadIdx.x < st) sm[threadIdx.x] += sm[threadIdx.x + st];
            __syncthreads();
        }
        float inv = 1.0f / fmaxf(sqrtf(sm[0]), 1e-12f);
        for (int d = threadIdx.x; d < ND; d += 256)
            g_zh[bx * ND + d] = __float2bfloat16(xr[d] * inv);
    } else {
        int t = (bx - NB) * 256 + threadIdx.x;
        const int N1 = NH * 2 * ND;                // 393216
        if (t < N1) g_W1h[t] = __float2bfloat16(W1[t]);
        else {
            int u = t - N1;
            if (u < NH * NH) g_W2h[u] = __float2bfloat16(W2[u]);
        }
    }
}

// ================= kernel B: featw (bx<40) | contrast (bx>=40) =============
// dynamic smem layout (contrast view):
constexpr int LZA = 776;   // za row stride (bf16)
constexpr int LZB = 776;   // zb row stride (bf16)
constexpr int LSS = 68;    // S partial row stride (fp32)
constexpr int B_ZA = 0;
constexpr int B_ZB = 16 * LZA * 2;                 // 24832
constexpr int B_S0 = B_ZB + 64 * LZB * 2;          // 124160
constexpr int B_S1 = B_S0 + 16 * LSS * 4;          // 128512
constexpr int B_SMEM = B_S1 + 16 * LSS * 4;        // 132864

__global__ void __launch_bounds__(256, 1) k_mid() {
    extern __shared__ __align__(16) char dyn[];
    __nv_bfloat16* za = reinterpret_cast<__nv_bfloat16*>(dyn + B_ZA);
    const int tid = threadIdx.x;
    const int w = tid >> 5, lane = tid & 31;

    if (blockIdx.x < 40) {
        // ---------- feature GEMM: t<8 -> A (off 0), t>=8 -> Bf (off 768) ----
        const int t = blockIdx.x;
        const bool isA = t < 8;
        const int rbase = (isA ? t : t - 8) * 16;
        const int off = isA ? 0 : ND;
        float* out = (isA ? g_A : g_Bf) + rbase * NH;

        for (int c = tid; c < 16 * (ND / 8); c += 256) {
            int r = c / (ND / 8), d8 = c % (ND / 8);
            *reinterpret_cast<uint4*>(za + r * LZA + d8 * 8) =
                *reinterpret_cast<const uint4*>(g_zh + (rbase + r) * ND + d8 * 8);
        }
        __syncthreads();

        int h0 = w * 32, h1 = h0 + 16;
        wmma::fragment<wmma::accumulator, 16, 16, 16, float> c0e, c0o, c1e, c1o;
        wmma::fill_fragment(c0e, 0.f); wmma::fill_fragment(c0o, 0.f);
        wmma::fill_fragment(c1e, 0.f); wmma::fill_fragment(c1o, 0.f);
#pragma unroll 4
        for (int kc = 0; kc < ND / 16; kc += 2) {
            wmma::fragment<wmma::matrix_a, 16, 16, 16, __nv_bfloat16, wmma::row_major> ae, ao;
            wmma::fragment<wmma::matrix_b, 16, 16, 16, __nv_bfloat16, wmma::col_major> b0e, b0o, b1e, b1o;
            wmma::load_matrix_sync(ae, za + kc * 16, LZA);
            wmma::load_matrix_sync(ao, za + (kc + 1) * 16, LZA);
            wmma::load_matrix_sync(b0e, g_W1h + h0 * (2 * ND) + off + kc * 16, 2 * ND);
            wmma::load_matrix_sync(b0o, g_W1h + h0 * (2 * ND) + off + (kc + 1) * 16, 2 * ND);
            wmma::load_matrix_sync(b1e, g_W1h + h1 * (2 * ND) + off + kc * 16, 2 * ND);
            wmma::load_matrix_sync(b1o, g_W1h + h1 * (2 * ND) + off + (kc + 1) * 16, 2 * ND);
            wmma::mma_sync(c0e, ae, b0e, c0e);
            wmma::mma_sync(c0o, ao, b0o, c0o);
            wmma::mma_sync(c1e, ae, b1e, c1e);
            wmma::mma_sync(c1o, ao, b1o, c1o);
        }
#pragma unroll
        for (int e = 0; e < c0e.num_elements; e++) { c0e.x[e] += c0o.x[e]; c1e.x[e] += c1o.x[e]; }
        wmma::store_matrix_sync(out + h0, c0e, NH, wmma::mem_row_major);
        wmma::store_matrix_sync(out + h1, c1e, NH, wmma::mem_row_major);
    } else {
        // ---------- contrastive partials: 16 i x 64 k, D split across warps -
        const int vb = blockIdx.x - 40;          // 0..63
        const int bx = vb >> 3;                  // i tile 0..7
        const int by = vb & 7;                   // k chunk 0..7
        const int ibase = bx * 16;
        const int kbase = by * 64;

        __nv_bfloat16* zb = reinterpret_cast<__nv_bfloat16*>(dyn + B_ZB);
        float* S0 = reinterpret_cast<float*>(dyn + B_S0);
        float* S1 = reinterpret_cast<float*>(dyn + B_S1);

        for (int c = tid; c < 16 * (ND / 8); c += 256) {
            int r = c / (ND / 8), d8 = c % (ND / 8);
            *reinterpret_cast<uint4*>(za + r * LZA + d8 * 8) =
                *reinterpret_cast<const uint4*>(g_zh + (ibase + r) * ND + d8 * 8);
        }
        for (int c = tid; c < 64 * (ND / 8); c += 256) {
            int r = c / (ND / 8), d8 = c % (ND / 8);
            *reinterpret_cast<uint4*>(zb + r * LZB + d8 * 8) =
                *reinterpret_cast<const uint4*>(g_zh + (kbase + r) * ND + d8 * 8);
        }
        __syncthreads();

        const int wn = w & 3;        // N tile (16 cols)
        const int wd = w >> 2;       // D half (384)
        const int kcol = wn * 16;
        const int d0 = wd * 384;

        wmma::fragment<wmma::accumulator, 16, 16, 16, float> cf0, cf1;
        wmma::fill_fragment(cf0, 0.f);
        wmma::fill_fragment(cf1, 0.f);
#pragma unroll 4
        for (int kc = 0; kc < 24; kc += 2) {
            wmma::fragment<wmma::matrix_a, 16, 16, 16, __nv_bfloat16, wmma::row_major> a0, a1;
            wmma::fragment<wmma::matrix_b, 16, 16, 16, __nv_bfloat16, wmma::col_major> b0, b1;
            wmma::load_matrix_sync(a0, za + d0 + kc * 16, LZA);
            wmma::load_matrix_sync(b0, zb + kcol * LZB + d0 + kc * 16, LZB);
            wmma::load_matrix_sync(a1, za + d0 + (kc + 1) * 16, LZA);
            wmma::load_matrix_sync(b1, zb + kcol * LZB + d0 + (kc + 1) * 16, LZB);
            wmma::mma_sync(cf0, a0, b0, cf0);
            wmma::mma_sync(cf1, a1, b1, cf1);
        }
#pragma unroll
        for (int e = 0; e < cf0.num_elements; e++) cf0.x[e] += cf1.x[e];
        wmma::store_matrix_sync((wd ? S1 : S0) + kcol, cf0, LSS, wmma::mem_row_major);
        __syncthreads();

        // epilogue: warp w reduces rows 2w, 2w+1 over 64 cols
#pragma unroll
        for (int rr = 2 * w; rr <= 2 * w + 1; rr++) {
            int i = ibase + rr;
            float dacc = 0.f, pacc = 0.f;
#pragma unroll
            for (int cc = 0; cc < 2; cc++) {
                int c = lane + cc * 32;
                int k = kbase + c;
                float s = S0[rr * LSS + c] + S1[rr * LSS + c];
                if (k != i) dacc += expf(TAU_INV * s);
                if (k > i && k < NQ) pacc += s;
            }
#pragma unroll
            for (int o = 16; o; o >>= 1) {
                dacc += __shfl_down_sync(0xffffffffu, dacc, o);
                pacc += __shfl_down_sync(0xffffffffu, pacc, o);
            }
            if (lane == 0) {
                g_denomp[i * 8 + by] = dacc;
                g_pairp[i * 8 + by] = pacc;
            }
        }
    }
}

// ================= kernel C: fused pair MLP, 4 i's per block ===============
constexpr int LDH = 264;
constexpr int LDW = 264;
constexpr int P_W2 = 0;
constexpr int P_H1 = 256 * LDW * 2;                 // 135168
constexpr int P_CS = P_H1 + 128 * LDH * 2;          // 202752
constexpr int P_ASH = P_CS + 8 * 512 * 4;           // 219136
constexpr int P_B2S = P_ASH + 4 * 256 * 4;          // 223232
constexpr int P_W3S = P_B2S + 256 * 4;              // 224256
constexpr int P_RED = P_W3S + 256 * 4;              // 225280
constexpr int P_SMEM = P_RED + 128 * 4;             // 225792
__global__ void __launch_bounds__(256, 1)
k_pair(const float* __restrict__ b1, const float* __restrict__ b2,
       const float* __restrict__ w3, const float* __restrict__ b3v) {
    extern __shared__ __align__(16) char dyn[];
    __nv_bfloat16* w2s = reinterpret_cast<__nv_bfloat16*>(dyn + P_W2);
    __nv_bfloat16* h1s = reinterpret_cast<__nv_bfloat16*>(dyn + P_H1);
    float* cscr = reinterpret_cast<float*>(dyn + P_CS);
    float* ash  = reinterpret_cast<float*>(dyn + P_ASH);
    float* b2s  = reinterpret_cast<float*>(dyn + P_B2S);
    float* w3s  = reinterpret_cast<float*>(dyn + P_W3S);
    float* red  = reinterpret_cast<float*>(dyn + P_RED);

    const int ibase = blockIdx.x * 4;
    const int j0 = blockIdx.y * 128;
    const int tid = threadIdx.x;

    {
        int h = tid;
        float bb = b1[h];
#pragma unroll
        for (int ii = 0; ii < 4; ii++)
            ash[ii * 256 + h] = g_A[(ibase + ii) * NH + h] + bb;
        b2s[h] = b2[h];
        w3s[h] = w3[h];
    }
    for (int c = tid; c < 256 * 32; c += 256) {
        int oo = c >> 5, q = c & 31;
        *reinterpret_cast<uint4*>(w2s + oo * LDW + q * 8) =
            *reinterpret_cast<const uint4*>(g_W2h + oo * NH + q * 8);
    }

    const int w = tid >> 5, lane = tid & 31;
    const int plocal = lane & 15, half = lane >> 4;
    float* cs = cscr + w * 512;
    float bacc = 0.f;

    for (int ii = 0; ii < 4; ii++) {
        const int i = ibase + ii;
        __syncthreads();   // prior mainloop reads done (and W2/ash ready on ii==0)
        // h1 = relu(ash[ii] + Bf[j]) bf16, 128 rows x 256
        const float* ai = ash + ii * 256;
        for (int c = tid; c < 128 * 64; c += 256) {
            int j = c >> 6, q4 = c & 63;
            float4 bv = *reinterpret_cast<const float4*>(g_Bf + (j0 + j) * NH + q4 * 4);
            float4 av = *reinterpret_cast<const float4*>(ai + q4 * 4);
            __nv_bfloat162 lo = __floats2bfloat162_rn(fmaxf(av.x + bv.x, 0.f),
                                                      fmaxf(av.y + bv.y, 0.f));
            __nv_bfloat162 hi = __floats2bfloat162_rn(fmaxf(av.z + bv.z, 0.f),
                                                      fmaxf(av.w + bv.w, 0.f));
            *reinterpret_cast<__nv_bfloat162*>(h1s + j * LDH + q4 * 4) = lo;
            *reinterpret_cast<__nv_bfloat162*>(h1s + j * LDH + q4 * 4 + 2) = hi;
        }
        __syncthreads();

        float accL = 0.f;
        for (int ot = 0; ot < 4; ot++) {
            const int o0 = ot * 16;
            wmma::fragment<wmma::accumulator, 16, 16, 16, float> cf0, cf1, cf2, cf3;
            wmma::fill_fragment(cf0, 0.f); wmma::fill_fragment(cf1, 0.f);
            wmma::fill_fragment(cf2, 0.f); wmma::fill_fragment(cf3, 0.f);
#pragma unroll
            for (int k = 0; k < 16; k++) {
                wmma::fragment<wmma::matrix_a, 16, 16, 16, __nv_bfloat16, wmma::row_major> af;
                wmma::fragment<wmma::matrix_b, 16, 16, 16, __nv_bfloat16, wmma::col_major> bf0, bf1, bf2, bf3;
                wmma::load_matrix_sync(af, h1s + w * 16 * LDH + k * 16, LDH);
                wmma::load_matrix_sync(bf0, w2s + (o0)       * LDW + k * 16, LDW);
                wmma::load_matrix_sync(bf1, w2s + (o0 + 64)  * LDW + k * 16, LDW);
                wmma::load_matrix_sync(bf2, w2s + (o0 + 128) * LDW + k * 16, LDW);
                wmma::load_matrix_sync(bf3, w2s + (o0 + 192) * LDW + k * 16, LDW);
                wmma::mma_sync(cf0, af, bf0, cf0);
                wmma::mma_sync(cf1, af, bf1, cf1);
                wmma::mma_sync(cf2, af, bf2, cf2);
                wmma::mma_sync(cf3, af, bf3, cf3);
            }
            // epilogue pass 1: tiles o0, o0+64
            wmma::store_matrix_sync(cs, cf0, 16, wmma::mem_row_major);
            wmma::store_matrix_sync(cs + 256, cf1, 16, wmma::mem_row_major);
            __syncwarp();
            {
                const float* cp0 = cs + plocal * 16 + half * 8;
                const float* cp1 = cp0 + 256;
                float s = 0.f;
#pragma unroll
                for (int q = 0; q < 8; q++) {
                    int oa = o0 + half * 8 + q, ob = o0 + 64 + half * 8 + q;
                    s += fmaxf(cp0[q] + b2s[oa], 0.f) * w3s[oa];
                    s += fmaxf(cp1[q] + b2s[ob], 0.f) * w3s[ob];
                }
                accL += s;
            }
            __syncwarp();
            // epilogue pass 2: tiles o0+128, o0+192
            wmma::store_matrix_sync(cs, cf2, 16, wmma::mem_row_major);
            wmma::store_matrix_sync(cs + 256, cf3, 16, wmma::mem_row_major);
            __syncwarp();
            {
                const float* cp0 = cs + plocal * 16 + half * 8;
                const float* cp1 = cp0 + 256;
                float s = 0.f;
#pragma unroll
                for (int q = 0; q < 8; q++) {
                    int oa = o0 + 128 + half * 8 + q, ob = o0 + 192 + half * 8 + q;
                    s += fmaxf(cp0[q] + b2s[oa], 0.f) * w3s[oa];
                    s += fmaxf(cp1[q] + b2s[ob], 0.f) * w3s[ob];
                }
                accL += s;
            }
            __syncwarp();
        }

        accL += __shfl_xor_sync(0xffffffffu, accL, 16);
        if (half == 0) red[w * 16 + plocal] = accL;
        __syncthreads();

        if (tid < 128) {
            int j = j0 + tid;
            if (j > i) {
                float logit = red[tid] + b3v[0];
                float lab = (j < NM) ? 1.f : 0.f;
                bacc += fmaxf(logit, 0.f) - logit * lab + log1pf(expf(-fabsf(logit)));
            }
        }
    }
    __syncthreads();

    // block reduce bacc (only tid<128 nonzero)
    red[tid & 127] = 0.f;   // not used; reuse cscr region for safety instead
    float* rr = cscr;       // 256 floats scratch
    rr[tid] = bacc;
    __syncthreads();
    for (int st = 128; st > 0; st >>= 1) {
        if (tid < st) rr[tid] += rr[tid + st];
        __syncthreads();
    }
    if (tid == 0) g_bcep[blockIdx.y * 32 + blockIdx.x] = rr[0];
}

// ================= kernel D: final reduce ==================================
__global__ void k_final(float* __restrict__ out) {
    __shared__ float s1[256];
    float b = (threadIdx.x < 128) ? g_bcep[threadIdx.x] : 0.f;
    s1[threadIdx.x] = b;
    __syncthreads();
    for (int st = 128; st > 0; st >>= 1) {
        if (threadIdx.x < st) s1[threadIdx.x] += s1[threadIdx.x + st];
        __syncthreads();
    }
    float bsum = s1[0];
    __syncthreads();

    float c = 0.f;
    if (threadIdx.x < NQ) {
        int i = threadIdx.x;
        float den = 0.f, pr = 0.f;
#pragma unroll
        for (int q = 0; q < 8; q++) {
            den += g_denomp[i * 8 + q];
            pr += g_pairp[i * 8 + q];
        }
        c = (float)(NQ - 1 - i) * logf(den) - TAU_INV * pr;
    }
    s1[threadIdx.x] = c;
    __syncthreads();
    for (int st = 128; st > 0; st >>= 1) {
        if (threadIdx.x < st) s1[threadIdx.x] += s1[threadIdx.x + st];
        __syncthreads();
    }
    if (threadIdx.x == 0) {
        float closs = (-2.0f * (float)(NQ - 1) / (float)NQ) * s1[0];
        out[0] = closs + bsum / PCOUNT;
    }
}

// ---------------- launch ----------------
extern "C" void kernel_launch(void* const* d_in, const int* in_sizes, int n_in,
                              void* d_out, int out_size) {
    const float* emb = (const float*)d_in[0];
    const float* W1  = (const float*)d_in[1];
    const float* b1  = (const float*)d_in[2];
    const float* W2  = (const float*)d_in[3];
    const float* b2  = (const float*)d_in[4];
    const float* W3  = (const float*)d_in[5];
    const float* b3  = (const float*)d_in[6];

    cudaFuncSetAttribute(k_mid, cudaFuncAttributeMaxDynamicSharedMemorySize, B_SMEM);
    cudaFuncSetAttribute(k_pair, cudaFuncAttributeMaxDynamicSharedMemorySize, P_SMEM);

    const int convBlocks = (NH * 2 * ND + NH * NH + 255) / 256;   // 1792
    k_prep<<<NB + convBlocks, 256>>>(emb, W1, W2);
    k_mid<<<40 + 64, 256, B_SMEM>>>();
    k_pair<<<dim3(32, 4), 256, P_SMEM>>>(b1, b2, W3, b3);
    k_final<<<1, 256>>>((float*)d_out);
}

// round 6
// speedup vs baseline: 3.3857x; 1.0740x over previous
#include <cuda_runtime.h>
#include <cuda_bf16.h>
#include <mma.h>
#include <cstdint>

using namespace nvcuda;

constexpr int NB = 512;   // batch B
constexpr int ND = 768;   // D
constexpr int NH = 256;   // H
constexpr int NQ = 128;   // n = B/4
constexpr int NM = 256;   // m = B/2
constexpr float TAU_INV = 2.0f;
constexpr float PCOUNT = 57280.0f;

// ---------------- scratch ----------------
__device__ __nv_bfloat16 g_zh[NB * ND];
__device__ __nv_bfloat16 g_W1h[NH * 2 * ND];
__device__ __nv_bfloat16 g_W2h[NH * NH];
__device__ float g_A[NQ * NH];
__device__ __nv_bfloat16 g_Bfh[NB * NH];
__device__ float g_denomp[NQ * 8];
__device__ float g_pairp[NQ * 8];
__device__ float g_bcep[128];
__device__ unsigned g_ctr;

// ================= kernel A: norm (bx<512) | W1/W2 bf16 convert ===========
__global__ void k_prep(const float* __restrict__ x,
                       const float* __restrict__ W1, const float* __restrict__ W2) {
    int bx = blockIdx.x;
    if (bx == 0 && threadIdx.x == 0) g_ctr = 0;   // reset last-block counter
    if (bx < NB) {
        const float* xr = x + bx * ND;
        float s = 0.f;
        for (int d = threadIdx.x; d < ND; d += 256) { float v = xr[d]; s += v * v; }
        __shared__ float sm[256];
        sm[threadIdx.x] = s;
        __syncthreads();
        for (int st = 128; st > 0; st >>= 1) {
            if (threadIdx.x < st) sm[threadIdx.x] += sm[threadIdx.x + st];
            __syncthreads();
        }
        float inv = 1.0f / fmaxf(sqrtf(sm[0]), 1e-12f);
        for (int p = threadIdx.x; p < ND / 2; p += 256) {
            __nv_bfloat162 v = __floats2bfloat162_rn(xr[2 * p] * inv, xr[2 * p + 1] * inv);
            *reinterpret_cast<__nv_bfloat162*>(g_zh + bx * ND + 2 * p) = v;
        }
    } else {
        const int N1 = NH * 2 * ND;                // 393216 (multiple of 1024)
        int base = (bx - NB) * 1024 + threadIdx.x * 4;
        const float* src;
        __nv_bfloat16* dst;
        int off;
        if (base < N1) { src = W1; dst = g_W1h; off = base; }
        else           { src = W2; dst = g_W2h; off = base - N1; }
        float4 v = *reinterpret_cast<const float4*>(src + off);
        __nv_bfloat162 lo = __floats2bfloat162_rn(v.x, v.y);
        __nv_bfloat162 hi = __floats2bfloat162_rn(v.z, v.w);
        *reinterpret_cast<__nv_bfloat162*>(dst + off) = lo;
        *reinterpret_cast<__nv_bfloat162*>(dst + off + 2) = hi;
    }
}

// ================= kernel B: featw (bx<40) | contrast (bx>=40) =============
constexpr int LZA = 776;   // za row stride (bf16)
constexpr int LZB = 776;   // zb row stride (bf16)
constexpr int LSS = 68;    // S partial row stride (fp32)
constexpr int B_ZA = 0;
constexpr int B_ZB = 16 * LZA * 2;                 // 24832
constexpr int B_S0 = B_ZB + 64 * LZB * 2;          // 124160
constexpr int B_S1 = B_S0 + 16 * LSS * 4;          // 128512
constexpr int B_SMEM = B_S1 + 16 * LSS * 4;        // 132864

__global__ void __launch_bounds__(256, 1) k_mid(const float* __restrict__ b1_unused) {
    extern __shared__ __align__(16) char dyn[];
    __nv_bfloat16* za = reinterpret_cast<__nv_bfloat16*>(dyn + B_ZA);
    const int tid = threadIdx.x;
    const int w = tid >> 5, lane = tid & 31;

    if (blockIdx.x < 40) {
        // ---------- feature GEMM: t<8 -> A (off 0), t>=8 -> Bf (off 768) ----
        const int t = blockIdx.x;
        const bool isA = t < 8;
        const int rbase = (isA ? t : t - 8) * 16;
        const int off = isA ? 0 : ND;

        for (int c = tid; c < 16 * (ND / 8); c += 256) {
            int r = c / (ND / 8), d8 = c % (ND / 8);
            *reinterpret_cast<uint4*>(za + r * LZA + d8 * 8) =
                *reinterpret_cast<const uint4*>(g_zh + (rbase + r) * ND + d8 * 8);
        }
        __syncthreads();

        int h0 = w * 32, h1 = h0 + 16;
        wmma::fragment<wmma::accumulator, 16, 16, 16, float> c0e, c0o, c1e, c1o;
        wmma::fill_fragment(c0e, 0.f); wmma::fill_fragment(c0o, 0.f);
        wmma::fill_fragment(c1e, 0.f); wmma::fill_fragment(c1o, 0.f);
#pragma unroll 4
        for (int kc = 0; kc < ND / 16; kc += 2) {
            wmma::fragment<wmma::matrix_a, 16, 16, 16, __nv_bfloat16, wmma::row_major> ae, ao;
            wmma::fragment<wmma::matrix_b, 16, 16, 16, __nv_bfloat16, wmma::col_major> b0e, b0o, b1e, b1o;
            wmma::load_matrix_sync(ae, za + kc * 16, LZA);
            wmma::load_matrix_sync(ao, za + (kc + 1) * 16, LZA);
            wmma::load_matrix_sync(b0e, g_W1h + h0 * (2 * ND) + off + kc * 16, 2 * ND);
            wmma::load_matrix_sync(b0o, g_W1h + h0 * (2 * ND) + off + (kc + 1) * 16, 2 * ND);
            wmma::load_matrix_sync(b1e, g_W1h + h1 * (2 * ND) + off + kc * 16, 2 * ND);
            wmma::load_matrix_sync(b1o, g_W1h + h1 * (2 * ND) + off + (kc + 1) * 16, 2 * ND);
            wmma::mma_sync(c0e, ae, b0e, c0e);
            wmma::mma_sync(c0o, ao, b0o, c0o);
            wmma::mma_sync(c1e, ae, b1e, c1e);
            wmma::mma_sync(c1o, ao, b1o, c1o);
        }
#pragma unroll
        for (int e = 0; e < c0e.num_elements; e++) { c0e.x[e] += c0o.x[e]; c1e.x[e] += c1o.x[e]; }

        if (isA) {
            float* out = g_A + rbase * NH;
            wmma::store_matrix_sync(out + h0, c0e, NH, wmma::mem_row_major);
            wmma::store_matrix_sync(out + h1, c1e, NH, wmma::mem_row_major);
        } else {
            // store to smem fp32 then convert to bf16 global
            float* cbuf = reinterpret_cast<float*>(dyn);    // reuse za (safe: mma reads done)
            __syncthreads();
            wmma::store_matrix_sync(cbuf + h0, c0e, 260, wmma::mem_row_major);
            wmma::store_matrix_sync(cbuf + h1, c1e, 260, wmma::mem_row_major);
            __syncthreads();
            for (int c = tid; c < 16 * 128; c += 256) {
                int r = c >> 7, p = c & 127;
                __nv_bfloat162 v = __floats2bfloat162_rn(cbuf[r * 260 + 2 * p],
                                                         cbuf[r * 260 + 2 * p + 1]);
                *reinterpret_cast<__nv_bfloat162*>(g_Bfh + (rbase + r) * NH + 2 * p) = v;
            }
        }
    } else {
        // ---------- contrastive partials: 16 i x 64 k, D split across warps -
        const int vb = blockIdx.x - 40;          // 0..63
        const int bx = vb >> 3;                  // i tile 0..7
        const int by = vb & 7;                   // k chunk 0..7
        const int ibase = bx * 16;
        const int kbase = by * 64;

        __nv_bfloat16* zb = reinterpret_cast<__nv_bfloat16*>(dyn + B_ZB);
        float* S0 = reinterpret_cast<float*>(dyn + B_S0);
        float* S1 = reinterpret_cast<float*>(dyn + B_S1);

        for (int c = tid; c < 16 * (ND / 8); c += 256) {
            int r = c / (ND / 8), d8 = c % (ND / 8);
            *reinterpret_cast<uint4*>(za + r * LZA + d8 * 8) =
                *reinterpret_cast<const uint4*>(g_zh + (ibase + r) * ND + d8 * 8);
        }
        for (int c = tid; c < 64 * (ND / 8); c += 256) {
            int r = c / (ND / 8), d8 = c % (ND / 8);
            *reinterpret_cast<uint4*>(zb + r * LZB + d8 * 8) =
                *reinterpret_cast<const uint4*>(g_zh + (kbase + r) * ND + d8 * 8);
        }
        __syncthreads();

        const int wn = w & 3;        // N tile (16 cols)
        const int wd = w >> 2;       // D half (384)
        const int kcol = wn * 16;
        const int d0 = wd * 384;

        wmma::fragment<wmma::accumulator, 16, 16, 16, float> cf0, cf1;
        wmma::fill_fragment(cf0, 0.f);
        wmma::fill_fragment(cf1, 0.f);
#pragma unroll 4
        for (int kc = 0; kc < 24; kc += 2) {
            wmma::fragment<wmma::matrix_a, 16, 16, 16, __nv_bfloat16, wmma::row_major> a0, a1;
            wmma::fragment<wmma::matrix_b, 16, 16, 16, __nv_bfloat16, wmma::col_major> b0, b1;
            wmma::load_matrix_sync(a0, za + d0 + kc * 16, LZA);
            wmma::load_matrix_sync(b0, zb + kcol * LZB + d0 + kc * 16, LZB);
            wmma::load_matrix_sync(a1, za + d0 + (kc + 1) * 16, LZA);
            wmma::load_matrix_sync(b1, zb + kcol * LZB + d0 + (kc + 1) * 16, LZB);
            wmma::mma_sync(cf0, a0, b0, cf0);
            wmma::mma_sync(cf1, a1, b1, cf1);
        }
#pragma unroll
        for (int e = 0; e < cf0.num_elements; e++) cf0.x[e] += cf1.x[e];
        wmma::store_matrix_sync((wd ? S1 : S0) + kcol, cf0, LSS, wmma::mem_row_major);
        __syncthreads();

#pragma unroll
        for (int rr = 2 * w; rr <= 2 * w + 1; rr++) {
            int i = ibase + rr;
            float dacc = 0.f, pacc = 0.f;
#pragma unroll
            for (int cc = 0; cc < 2; cc++) {
                int c = lane + cc * 32;
                int k = kbase + c;
                float s = S0[rr * LSS + c] + S1[rr * LSS + c];
                if (k != i) dacc += expf(TAU_INV * s);
                if (k > i && k < NQ) pacc += s;
            }
#pragma unroll
            for (int o = 16; o; o >>= 1) {
                dacc += __shfl_down_sync(0xffffffffu, dacc, o);
                pacc += __shfl_down_sync(0xffffffffu, pacc, o);
            }
            if (lane == 0) {
                g_denomp[i * 8 + by] = dacc;
                g_pairp[i * 8 + by] = pacc;
            }
        }
    }
}

// ================= kernel C: fused pair MLP + final reduce =================
constexpr int LDH = 264;
constexpr int LDW = 264;
constexpr int P_W2 = 0;
constexpr int P_H1 = 256 * LDW * 2;                 // 135168
constexpr int P_CS = P_H1 + 128 * LDH * 2;          // 202752
constexpr int P_ASH = P_CS + 8 * 512 * 4;           // 219136  (4*256 bf16)
constexpr int P_B2S = P_ASH + 4 * 256 * 2;          // 221184
constexpr int P_W3S = P_B2S + 256 * 4;              // 222208
constexpr int P_RED = P_W3S + 256 * 4;              // 223232
constexpr int P_SMEM = P_RED + 128 * 4;             // 223744
__global__ void __launch_bounds__(256, 1)
k_pair(const float* __restrict__ b1, const float* __restrict__ b2,
       const float* __restrict__ w3, const float* __restrict__ b3v,
       float* __restrict__ out) {
    extern __shared__ __align__(16) char dyn[];
    __nv_bfloat16* w2s = reinterpret_cast<__nv_bfloat16*>(dyn + P_W2);
    __nv_bfloat16* h1s = reinterpret_cast<__nv_bfloat16*>(dyn + P_H1);
    float* cscr = reinterpret_cast<float*>(dyn + P_CS);
    __nv_bfloat16* ashh = reinterpret_cast<__nv_bfloat16*>(dyn + P_ASH);
    float* b2s  = reinterpret_cast<float*>(dyn + P_B2S);
    float* w3s  = reinterpret_cast<float*>(dyn + P_W3S);
    float* red  = reinterpret_cast<float*>(dyn + P_RED);

    const int ibase = blockIdx.x * 4;
    const int j0 = blockIdx.y * 128;
    const int tid = threadIdx.x;

    {
        int h = tid;
        float bb = b1[h];
#pragma unroll
        for (int ii = 0; ii < 4; ii++)
            ashh[ii * 256 + h] = __float2bfloat16(g_A[(ibase + ii) * NH + h] + bb);
        b2s[h] = b2[h];
        w3s[h] = w3[h];
    }
    for (int c = tid; c < 256 * 32; c += 256) {
        int oo = c >> 5, q = c & 31;
        *reinterpret_cast<uint4*>(w2s + oo * LDW + q * 8) =
            *reinterpret_cast<const uint4*>(g_W2h + oo * NH + q * 8);
    }

    const int w = tid >> 5, lane = tid & 31;
    const int plocal = lane & 15, half = lane >> 4;
    float* cs = cscr + w * 512;
    float bacc = 0.f;
    const __nv_bfloat162 zero2 = __floats2bfloat162_rn(0.f, 0.f);

    for (int ii = 0; ii < 4; ii++) {
        const int i = ibase + ii;
        __syncthreads();   // prior mainloop reads done (and W2/ash ready on ii==0)
        // h1 = relu(ash[ii] + Bfh[j]) in packed bf16, 128 rows x 256
        const __nv_bfloat16* ai = ashh + ii * 256;
        for (int c = tid; c < 128 * 32; c += 256) {
            int j = c >> 5, g = c & 31;
            uint4 bv = *reinterpret_cast<const uint4*>(g_Bfh + (j0 + j) * NH + g * 8);
            const __nv_bfloat162* ap = reinterpret_cast<const __nv_bfloat162*>(ai + g * 8);
            __nv_bfloat162* hv = reinterpret_cast<__nv_bfloat162*>(&bv);
#pragma unroll
            for (int q = 0; q < 4; q++) hv[q] = __hmax2(__hadd2(hv[q], ap[q]), zero2);
            *reinterpret_cast<uint4*>(h1s + j * LDH + g * 8) = bv;
        }
        __syncthreads();

        float accL = 0.f;
        for (int ot = 0; ot < 4; ot++) {
            const int o0 = ot * 16;
            wmma::fragment<wmma::accumulator, 16, 16, 16, float> cf0, cf1, cf2, cf3;
            wmma::fill_fragment(cf0, 0.f); wmma::fill_fragment(cf1, 0.f);
            wmma::fill_fragment(cf2, 0.f); wmma::fill_fragment(cf3, 0.f);
#pragma unroll
            for (int k = 0; k < 16; k++) {
                wmma::fragment<wmma::matrix_a, 16, 16, 16, __nv_bfloat16, wmma::row_major> af;
                wmma::fragment<wmma::matrix_b, 16, 16, 16, __nv_bfloat16, wmma::col_major> bf0, bf1, bf2, bf3;
                wmma::load_matrix_sync(af, h1s + w * 16 * LDH + k * 16, LDH);
                wmma::load_matrix_sync(bf0, w2s + (o0)       * LDW + k * 16, LDW);
                wmma::load_matrix_sync(bf1, w2s + (o0 + 64)  * LDW + k * 16, LDW);
                wmma::load_matrix_sync(bf2, w2s + (o0 + 128) * LDW + k * 16, LDW);
                wmma::load_matrix_sync(bf3, w2s + (o0 + 192) * LDW + k * 16, LDW);
                wmma::mma_sync(cf0, af, bf0, cf0);
                wmma::mma_sync(cf1, af, bf1, cf1);
                wmma::mma_sync(cf2, af, bf2, cf2);
                wmma::mma_sync(cf3, af, bf3, cf3);
            }
            wmma::store_matrix_sync(cs, cf0, 16, wmma::mem_row_major);
            wmma::store_matrix_sync(cs + 256, cf1, 16, wmma::mem_row_major);
            __syncwarp();
            {
                const float* cp0 = cs + plocal * 16 + half * 8;
                const float* cp1 = cp0 + 256;
                float s = 0.f;
#pragma unroll
                for (int q = 0; q < 8; q++) {
                    int oa = o0 + half * 8 + q, ob = o0 + 64 + half * 8 + q;
                    s += fmaxf(cp0[q] + b2s[oa], 0.f) * w3s[oa];
                    s += fmaxf(cp1[q] + b2s[ob], 0.f) * w3s[ob];
                }
                accL += s;
            }
            __syncwarp();
            wmma::store_matrix_sync(cs, cf2, 16, wmma::mem_row_major);
            wmma::store_matrix_sync(cs + 256, cf3, 16, wmma::mem_row_major);
            __syncwarp();
            {
                const float* cp0 = cs + plocal * 16 + half * 8;
                const float* cp1 = cp0 + 256;
                float s = 0.f;
#pragma unroll
                for (int q = 0; q < 8; q++) {
                    int oa = o0 + 128 + half * 8 + q, ob = o0 + 192 + half * 8 + q;
                    s += fmaxf(cp0[q] + b2s[oa], 0.f) * w3s[oa];
                    s += fmaxf(cp1[q] + b2s[ob], 0.f) * w3s[ob];
                }
                accL += s;
            }
            __syncwarp();
        }

        accL += __shfl_xor_sync(0xffffffffu, accL, 16);
        if (half == 0) red[w * 16 + plocal] = accL;
        __syncthreads();

        if (tid < 128) {
            int j = j0 + tid;
            if (j > i) {
                float logit = red[tid] + b3v[0];
                float lab = (j < NM) ? 1.f : 0.f;
                bacc += fmaxf(logit, 0.f) - logit * lab + log1pf(expf(-fabsf(logit)));
            }
        }
    }
    __syncthreads();

    // block reduce bacc
    float* rr = cscr;
    rr[tid] = bacc;
    __syncthreads();
    for (int st = 128; st > 0; st >>= 1) {
        if (tid < st) rr[tid] += rr[tid + st];
        __syncthreads();
    }
    __shared__ bool isLast;
    if (tid == 0) {
        g_bcep[blockIdx.y * 32 + blockIdx.x] = rr[0];
        __threadfence();
        unsigned v = atomicAdd(&g_ctr, 1u);
        isLast = (v == 127u);
    }
    __syncthreads();
    if (!isLast) return;

    // ----- final reduce (last block only, deterministic order) -----
    float b = (tid < 128) ? g_bcep[tid] : 0.f;
    rr[tid] = b;
    __syncthreads();
    for (int st = 128; st > 0; st >>= 1) {
        if (tid < st) rr[tid] += rr[tid + st];
        __syncthreads();
    }
    float bsum = rr[0];
    __syncthreads();

    float c = 0.f;
    if (tid < NQ) {
        int i = tid;
        float den = 0.f, pr = 0.f;
#pragma unroll
        for (int q = 0; q < 8; q++) {
            den += g_denomp[i * 8 + q];
            pr += g_pairp[i * 8 + q];
        }
        c = (float)(NQ - 1 - i) * logf(den) - TAU_INV * pr;
    }
    rr[tid] = c;
    __syncthreads();
    for (int st = 128; st > 0; st >>= 1) {
        if (tid < st) rr[tid] += rr[tid + st];
        __syncthreads();
    }
    if (tid == 0) {
        float closs = (-2.0f * (float)(NQ - 1) / (float)NQ) * rr[0];
        out[0] = closs + bsum / PCOUNT;
    }
}

// ---------------- launch ----------------
extern "C" void kernel_launch(void* const* d_in, const int* in_sizes, int n_in,
                              void* d_out, int out_size) {
    const float* emb = (const float*)d_in[0];
    const float* W1  = (const float*)d_in[1];
    const float* b1  = (const float*)d_in[2];
    const float* W2  = (const float*)d_in[3];
    const float* b2  = (const float*)d_in[4];
    const float* W3  = (const float*)d_in[5];
    const float* b3  = (const float*)d_in[6];

    cudaFuncSetAttribute(k_mid, cudaFuncAttributeMaxDynamicSharedMemorySize, B_SMEM);
    cudaFuncSetAttribute(k_pair, cudaFuncAttributeMaxDynamicSharedMemorySize, P_SMEM);

    k_prep<<<NB + 448, 256>>>(emb, W1, W2);
    k_mid<<<40 + 64, 256, B_SMEM>>>(b1);
    k_pair<<<dim3(32, 4), 256, P_SMEM>>>(b1, b2, W3, b3, (float*)d_out);
}

// round 8
// speedup vs baseline: 4.0136x; 1.1854x over previous
#include <cuda_runtime.h>
#include <cuda_bf16.h>
#include <mma.h>
#include <cstdint>

using namespace nvcuda;

constexpr int NB = 512;   // batch B
constexpr int ND = 768;   // D
constexpr int NH = 256;   // H
constexpr int NQ = 128;   // n = B/4
constexpr int NM = 256;   // m = B/2
constexpr float TAU_INV = 2.0f;
constexpr float PCOUNT = 57280.0f;

// ---------------- scratch ----------------
__device__ __nv_bfloat16 g_zh[NB * ND];
__device__ __nv_bfloat16 g_W1h[NH * 2 * ND];
__device__ __nv_bfloat16 g_W2h[NH * NH];
__device__ float g_A[NQ * NH];
__device__ __nv_bfloat16 g_Bfh[NB * NH];
__device__ float g_denomp[NQ * 8];
__device__ float g_pairp[NQ * 8];
__device__ float g_bcep[128];
__device__ unsigned g_ctr;

// ================= kernel A: norm (bx<512) | W1/W2 bf16 convert ===========
__global__ void k_prep(const float* __restrict__ x,
                       const float* __restrict__ W1, const float* __restrict__ W2) {
    int bx = blockIdx.x;
    if (bx == 0 && threadIdx.x == 0) g_ctr = 0;
    if (bx < NB) {
        const float* xr = x + bx * ND;
        float s = 0.f;
        for (int d = threadIdx.x; d < ND; d += 256) { float v = xr[d]; s += v * v; }
        __shared__ float sm[256];
        sm[threadIdx.x] = s;
        __syncthreads();
        for (int st = 128; st > 0; st >>= 1) {
            if (threadIdx.x < st) sm[threadIdx.x] += sm[threadIdx.x + st];
            __syncthreads();
        }
        float inv = 1.0f / fmaxf(sqrtf(sm[0]), 1e-12f);
        for (int p = threadIdx.x; p < ND / 2; p += 256) {
            __nv_bfloat162 v = __floats2bfloat162_rn(xr[2 * p] * inv, xr[2 * p + 1] * inv);
            *reinterpret_cast<__nv_bfloat162*>(g_zh + bx * ND + 2 * p) = v;
        }
    } else {
        const int N1 = NH * 2 * ND;
        int base = (bx - NB) * 1024 + threadIdx.x * 4;
        const float* src;
        __nv_bfloat16* dst;
        int off;
        if (base < N1) { src = W1; dst = g_W1h; off = base; }
        else           { src = W2; dst = g_W2h; off = base - N1; }
        float4 v = *reinterpret_cast<const float4*>(src + off);
        *reinterpret_cast<__nv_bfloat162*>(dst + off)     = __floats2bfloat162_rn(v.x, v.y);
        *reinterpret_cast<__nv_bfloat162*>(dst + off + 2) = __floats2bfloat162_rn(v.z, v.w);
    }
}

// ================= kernel B: featw (bx<40) | contrast (bx>=40) =============
constexpr int LZA = 776;
constexpr int LZB = 776;
constexpr int LSS = 68;
constexpr int B_ZA = 0;
constexpr int B_ZB = 16 * LZA * 2;                 // 24832
constexpr int B_S0 = B_ZB + 64 * LZB * 2;          // 124160
constexpr int B_S1 = B_S0 + 16 * LSS * 4;          // 128512
constexpr int B_SMEM = B_S1 + 16 * LSS * 4;        // 132864

__global__ void __launch_bounds__(256, 1) k_mid() {
    extern __shared__ __align__(16) char dyn[];
    __nv_bfloat16* za = reinterpret_cast<__nv_bfloat16*>(dyn + B_ZA);
    const int tid = threadIdx.x;
    const int w = tid >> 5, lane = tid & 31;

    if (blockIdx.x < 40) {
        const int t = blockIdx.x;
        const bool isA = t < 8;
        const int rbase = (isA ? t : t - 8) * 16;
        const int off = isA ? 0 : ND;

        for (int c = tid; c < 16 * (ND / 8); c += 256) {
            int r = c / (ND / 8), d8 = c % (ND / 8);
            *reinterpret_cast<uint4*>(za + r * LZA + d8 * 8) =
                *reinterpret_cast<const uint4*>(g_zh + (rbase + r) * ND + d8 * 8);
        }
        __syncthreads();

        int h0 = w * 32, h1 = h0 + 16;
        wmma::fragment<wmma::accumulator, 16, 16, 16, float> c0e, c0o, c1e, c1o;
        wmma::fill_fragment(c0e, 0.f); wmma::fill_fragment(c0o, 0.f);
        wmma::fill_fragment(c1e, 0.f); wmma::fill_fragment(c1o, 0.f);
#pragma unroll 4
        for (int kc = 0; kc < ND / 16; kc += 2) {
            wmma::fragment<wmma::matrix_a, 16, 16, 16, __nv_bfloat16, wmma::row_major> ae, ao;
            wmma::fragment<wmma::matrix_b, 16, 16, 16, __nv_bfloat16, wmma::col_major> b0e, b0o, b1e, b1o;
            wmma::load_matrix_sync(ae, za + kc * 16, LZA);
            wmma::load_matrix_sync(ao, za + (kc + 1) * 16, LZA);
            wmma::load_matrix_sync(b0e, g_W1h + h0 * (2 * ND) + off + kc * 16, 2 * ND);
            wmma::load_matrix_sync(b0o, g_W1h + h0 * (2 * ND) + off + (kc + 1) * 16, 2 * ND);
            wmma::load_matrix_sync(b1e, g_W1h + h1 * (2 * ND) + off + kc * 16, 2 * ND);
            wmma::load_matrix_sync(b1o, g_W1h + h1 * (2 * ND) + off + (kc + 1) * 16, 2 * ND);
            wmma::mma_sync(c0e, ae, b0e, c0e);
            wmma::mma_sync(c0o, ao, b0o, c0o);
            wmma::mma_sync(c1e, ae, b1e, c1e);
            wmma::mma_sync(c1o, ao, b1o, c1o);
        }
#pragma unroll
        for (int e = 0; e < c0e.num_elements; e++) { c0e.x[e] += c0o.x[e]; c1e.x[e] += c1o.x[e]; }

        if (isA) {
            float* out = g_A + rbase * NH;
            wmma::store_matrix_sync(out + h0, c0e, NH, wmma::mem_row_major);
            wmma::store_matrix_sync(out + h1, c1e, NH, wmma::mem_row_major);
        } else {
            float* cbuf = reinterpret_cast<float*>(dyn);
            __syncthreads();
            wmma::store_matrix_sync(cbuf + h0, c0e, 260, wmma::mem_row_major);
            wmma::store_matrix_sync(cbuf + h1, c1e, 260, wmma::mem_row_major);
            __syncthreads();
            for (int c = tid; c < 16 * 128; c += 256) {
                int r = c >> 7, p = c & 127;
                __nv_bfloat162 v = __floats2bfloat162_rn(cbuf[r * 260 + 2 * p],
                                                         cbuf[r * 260 + 2 * p + 1]);
                *reinterpret_cast<__nv_bfloat162*>(g_Bfh + (rbase + r) * NH + 2 * p) = v;
            }
        }
    } else {
        const int vb = blockIdx.x - 40;
        const int bx = vb >> 3;
        const int by = vb & 7;
        const int ibase = bx * 16;
        const int kbase = by * 64;

        __nv_bfloat16* zb = reinterpret_cast<__nv_bfloat16*>(dyn + B_ZB);
        float* S0 = reinterpret_cast<float*>(dyn + B_S0);
        float* S1 = reinterpret_cast<float*>(dyn + B_S1);

        for (int c = tid; c < 16 * (ND / 8); c += 256) {
            int r = c / (ND / 8), d8 = c % (ND / 8);
            *reinterpret_cast<uint4*>(za + r * LZA + d8 * 8) =
                *reinterpret_cast<const uint4*>(g_zh + (ibase + r) * ND + d8 * 8);
        }
        for (int c = tid; c < 64 * (ND / 8); c += 256) {
            int r = c / (ND / 8), d8 = c % (ND / 8);
            *reinterpret_cast<uint4*>(zb + r * LZB + d8 * 8) =
                *reinterpret_cast<const uint4*>(g_zh + (kbase + r) * ND + d8 * 8);
        }
        __syncthreads();

        const int wn = w & 3;
        const int wd = w >> 2;
        const int kcol = wn * 16;
        const int d0 = wd * 384;

        wmma::fragment<wmma::accumulator, 16, 16, 16, float> cf0, cf1;
        wmma::fill_fragment(cf0, 0.f);
        wmma::fill_fragment(cf1, 0.f);
#pragma unroll 4
        for (int kc = 0; kc < 24; kc += 2) {
            wmma::fragment<wmma::matrix_a, 16, 16, 16, __nv_bfloat16, wmma::row_major> a0, a1;
            wmma::fragment<wmma::matrix_b, 16, 16, 16, __nv_bfloat16, wmma::col_major> b0, b1;
            wmma::load_matrix_sync(a0, za + d0 + kc * 16, LZA);
            wmma::load_matrix_sync(b0, zb + kcol * LZB + d0 + kc * 16, LZB);
            wmma::load_matrix_sync(a1, za + d0 + (kc + 1) * 16, LZA);
            wmma::load_matrix_sync(b1, zb + kcol * LZB + d0 + (kc + 1) * 16, LZB);
            wmma::mma_sync(cf0, a0, b0, cf0);
            wmma::mma_sync(cf1, a1, b1, cf1);
        }
#pragma unroll
        for (int e = 0; e < cf0.num_elements; e++) cf0.x[e] += cf1.x[e];
        wmma::store_matrix_sync((wd ? S1 : S0) + kcol, cf0, LSS, wmma::mem_row_major);
        __syncthreads();

#pragma unroll
        for (int rr = 2 * w; rr <= 2 * w + 1; rr++) {
            int i = ibase + rr;
            float dacc = 0.f, pacc = 0.f;
#pragma unroll
            for (int cc = 0; cc < 2; cc++) {
                int c = lane + cc * 32;
                int k = kbase + c;
                float s = S0[rr * LSS + c] + S1[rr * LSS + c];
                if (k != i) dacc += expf(TAU_INV * s);
                if (k > i && k < NQ) pacc += s;
            }
#pragma unroll
            for (int o = 16; o; o >>= 1) {
                dacc += __shfl_down_sync(0xffffffffu, dacc, o);
                pacc += __shfl_down_sync(0xffffffffu, pacc, o);
            }
            if (lane == 0) {
                g_denomp[i * 8 + by] = dacc;
                g_pairp[i * 8 + by] = pacc;
            }
        }
    }
}

// ================= kernel C: pair MLP, W2 resident in REGISTERS ============
constexpr int LDH = 264;
constexpr int P_H1 = 0;                            // 128*264*2 = 67584
constexpr int P_CS = 67584;                        // 8*512*4  = 16384
constexpr int P_PART = P_CS + 16384;               // 128*8*4  = 4096
constexpr int P_ASH = P_PART + 4096;               // 4*256*2  = 2048
constexpr int P_B2S = P_ASH + 2048;                // 1024
constexpr int P_W3S = P_B2S + 1024;                // 1024
constexpr int P_RR  = P_W3S + 1024;                // 1024
constexpr int P_SMEM = P_RR + 1024;                // 93184
__global__ void __launch_bounds__(256, 1)
k_pair(const float* __restrict__ b1, const float* __restrict__ b2,
       const float* __restrict__ w3, const float* __restrict__ b3v,
       float* __restrict__ out) {
    extern __shared__ __align__(16) char dyn[];
    __nv_bfloat16* h1s = reinterpret_cast<__nv_bfloat16*>(dyn + P_H1);
    float* cscr = reinterpret_cast<float*>(dyn + P_CS);
    float* part = reinterpret_cast<float*>(dyn + P_PART);
    __nv_bfloat16* ashh = reinterpret_cast<__nv_bfloat16*>(dyn + P_ASH);
    float* b2s = reinterpret_cast<float*>(dyn + P_B2S);
    float* w3s = reinterpret_cast<float*>(dyn + P_W3S);
    float* rr  = reinterpret_cast<float*>(dyn + P_RR);

    const int ibase = blockIdx.x * 4;
    const int j0 = blockIdx.y * 128;
    const int tid = threadIdx.x;
    const int w = tid >> 5, lane = tid & 31;
    const int plocal = lane & 15, half = lane >> 4;
    const int c0 = w * 32;   // this warp's 32 output columns

    // stage small tensors
    {
        int h = tid;
        float bb = b1[h];
#pragma unroll
        for (int ii = 0; ii < 4; ii++)
            ashh[ii * 256 + h] = __float2bfloat16(g_A[(ibase + ii) * NH + h] + bb);
        b2s[h] = b2[h];
        w3s[h] = w3[h];
    }

    // persistent W2 fragments: warp w owns cols [c0, c0+32), all 16 k-steps
    wmma::fragment<wmma::matrix_b, 16, 16, 16, __nv_bfloat16, wmma::col_major> bf0[16], bf1[16];
#pragma unroll
    for (int k = 0; k < 16; k++) {
        wmma::load_matrix_sync(bf0[k], g_W2h + c0 * NH + k * 16, NH);
        wmma::load_matrix_sync(bf1[k], g_W2h + (c0 + 16) * NH + k * 16, NH);
    }

    float* cs = cscr + w * 512;
    const __nv_bfloat162 zero2 = __floats2bfloat162_rn(0.f, 0.f);
    float bacc = 0.f;

    for (int ii = 0; ii < 4; ii++) {
        const int i = ibase + ii;
        __syncthreads();   // prev iter h1 reads + part reads done (ash ready on ii==0)

        // h1 = relu(ash[ii] + Bfh[j]) packed bf16, 128 rows x 256
        const __nv_bfloat16* ai = ashh + ii * 256;
        for (int c = tid; c < 128 * 32; c += 256) {
            int j = c >> 5, g = c & 31;
            uint4 bv = *reinterpret_cast<const uint4*>(g_Bfh + (j0 + j) * NH + g * 8);
            const __nv_bfloat162* ap = reinterpret_cast<const __nv_bfloat162*>(ai + g * 8);
            __nv_bfloat162* hv = reinterpret_cast<__nv_bfloat162*>(&bv);
#pragma unroll
            for (int q = 0; q < 4; q++) hv[q] = __hmax2(__hadd2(hv[q], ap[q]), zero2);
            *reinterpret_cast<uint4*>(h1s + j * LDH + g * 8) = bv;
        }
        __syncthreads();

        // mainloop: 8 M-tiles x (16 k-steps, 2 col-tiles)
        for (int mt = 0; mt < 8; mt++) {
            wmma::fragment<wmma::accumulator, 16, 16, 16, float> acc0, acc1;
            wmma::fill_fragment(acc0, 0.f);
            wmma::fill_fragment(acc1, 0.f);
#pragma unroll
            for (int k = 0; k < 16; k++) {
                wmma::fragment<wmma::matrix_a, 16, 16, 16, __nv_bfloat16, wmma::row_major> af;
                wmma::load_matrix_sync(af, h1s + mt * 16 * LDH + k * 16, LDH);
                wmma::mma_sync(acc0, af, bf0[k], acc0);
                wmma::mma_sync(acc1, af, bf1[k], acc1);
            }
            wmma::store_matrix_sync(cs, acc0, 16, wmma::mem_row_major);
            wmma::store_matrix_sync(cs + 256, acc1, 16, wmma::mem_row_major);
            __syncwarp();
            {
                const float* cp = cs + half * 256 + plocal * 16;
                const int cb = c0 + half * 16;
                float s = 0.f;
#pragma unroll
                for (int q = 0; q < 16; q++)
                    s += fmaxf(cp[q] + b2s[cb + q], 0.f) * w3s[cb + q];
                s += __shfl_down_sync(0xffffffffu, s, 16);
                if (half == 0) part[(mt * 16 + plocal) * 8 + w] = s;
            }
            __syncwarp();
        }
        __syncthreads();

        if (tid < 128) {
            int j = j0 + tid;
            if (j > i) {
                float logit = b3v[0];
#pragma unroll
                for (int q = 0; q < 8; q++) logit += part[tid * 8 + q];
                float lab = (j < NM) ? 1.f : 0.f;
                bacc += fmaxf(logit, 0.f) - logit * lab + log1pf(expf(-fabsf(logit)));
            }
        }
    }
    __syncthreads();

    // block reduce bacc
    rr[tid] = bacc;
    __syncthreads();
    for (int st = 128; st > 0; st >>= 1) {
        if (tid < st) rr[tid] += rr[tid + st];
        __syncthreads();
    }
    __shared__ bool isLast;
    if (tid == 0) {
        g_bcep[blockIdx.y * 32 + blockIdx.x] = rr[0];
        __threadfence();
        unsigned v = atomicAdd(&g_ctr, 1u);
        isLast = (v == 127u);
    }
    __syncthreads();
    if (!isLast) return;

    // ----- final reduce (last block, deterministic order) -----
    float b = (tid < 128) ? g_bcep[tid] : 0.f;
    rr[tid] = b;
    __syncthreads();
    for (int st = 128; st > 0; st >>= 1) {
        if (tid < st) rr[tid] += rr[tid + st];
        __syncthreads();
    }
    float bsum = rr[0];
    __syncthreads();

    float c = 0.f;
    if (tid < NQ) {
        int i = tid;
        float den = 0.f, pr = 0.f;
#pragma unroll
        for (int q = 0; q < 8; q++) {
            den += g_denomp[i * 8 + q];
            pr += g_pairp[i * 8 + q];
        }
        c = (float)(NQ - 1 - i) * logf(den) - TAU_INV * pr;
    }
    rr[tid] = c;
    __syncthreads();
    for (int st = 128; st > 0; st >>= 1) {
        if (tid < st) rr[tid] += rr[tid + st];
        __syncthreads();
    }
    if (tid == 0) {
        float closs = (-2.0f * (float)(NQ - 1) / (float)NQ) * rr[0];
        out[0] = closs + bsum / PCOUNT;
    }
}

// ---------------- launch ----------------
extern "C" void kernel_launch(void* const* d_in, const int* in_sizes, int n_in,
                              void* d_out, int out_size) {
    const float* emb = (const float*)d_in[0];
    const float* W1  = (const float*)d_in[1];
    const float* b1  = (const float*)d_in[2];
    const float* W2  = (const float*)d_in[3];
    const float* b2  = (const float*)d_in[4];
    const float* W3  = (const float*)d_in[5];
    const float* b3  = (const float*)d_in[6];

    cudaFuncSetAttribute(k_mid, cudaFuncAttributeMaxDynamicSharedMemorySize, B_SMEM);
    cudaFuncSetAttribute(k_pair, cudaFuncAttributeMaxDynamicSharedMemorySize, P_SMEM);

    k_prep<<<NB + 448, 256>>>(emb, W1, W2);
    k_mid<<<40 + 64, 256, B_SMEM>>>();
    k_pair<<<dim3(32, 4), 256, P_SMEM>>>(b1, b2, W3, b3, (float*)d_out);
}

// round 9
// speedup vs baseline: 4.1899x; 1.0439x over previous
#include <cuda_runtime.h>
#include <cuda_bf16.h>
#include <mma.h>
#include <cstdint>

using namespace nvcuda;

constexpr int NB = 512;   // batch B
constexpr int ND = 768;   // D
constexpr int NH = 256;   // H
constexpr int NQ = 128;   // n = B/4
constexpr int NM = 256;   // m = B/2
constexpr float TAU_INV = 2.0f;
constexpr float PCOUNT = 57280.0f;

// ---------------- scratch ----------------
__device__ __nv_bfloat16 g_zh[NB * ND];
__device__ __nv_bfloat16 g_W1h[NH * 2 * ND];
__device__ __nv_bfloat16 g_W2h[NH * NH];
__device__ float g_A[NQ * NH];
__device__ __nv_bfloat16 g_Bfh[NB * NH];
__device__ float g_denomp[NQ * 8];
__device__ float g_pairp[NQ * 8];
__device__ float g_bcep[128];
__device__ unsigned g_ctr;

// ================= kernel A: norm (bx<128, 4 rows each) | W1/W2 convert ====
__global__ void k_prep(const float* __restrict__ x,
                       const float* __restrict__ W1, const float* __restrict__ W2) {
    int bx = blockIdx.x;
    if (bx == 0 && threadIdx.x == 0) g_ctr = 0;
    if (bx < 128) {
        __shared__ float sm[8];
        const int w = threadIdx.x >> 5, lane = threadIdx.x & 31;
        const int r = bx * 4 + (w >> 1);
        const int hoff = (w & 1) * 384;
        const float* xr = x + r * ND;
        float s = 0.f;
#pragma unroll
        for (int q = 0; q < 12; q++) { float v = xr[hoff + lane + q * 32]; s += v * v; }
#pragma unroll
        for (int o = 16; o; o >>= 1) s += __shfl_down_sync(0xffffffffu, s, o);
        if (lane == 0) sm[w] = s;
        __syncthreads();
        float inv = 1.0f / fmaxf(sqrtf(sm[w & ~1] + sm[(w & ~1) + 1]), 1e-12f);
        const int poff = (w & 1) * 192;
#pragma unroll
        for (int q = 0; q < 6; q++) {
            int p = poff + lane + q * 32;
            __nv_bfloat162 v = __floats2bfloat162_rn(xr[2 * p] * inv, xr[2 * p + 1] * inv);
            *reinterpret_cast<__nv_bfloat162*>(g_zh + r * ND + 2 * p) = v;
        }
    } else {
        const int N1 = NH * 2 * ND;
        int base = (bx - 128) * 1024 + threadIdx.x * 4;
        const float* src;
        __nv_bfloat16* dst;
        int off;
        if (base < N1) { src = W1; dst = g_W1h; off = base; }
        else           { src = W2; dst = g_W2h; off = base - N1; }
        float4 v = *reinterpret_cast<const float4*>(src + off);
        *reinterpret_cast<__nv_bfloat162*>(dst + off)     = __floats2bfloat162_rn(v.x, v.y);
        *reinterpret_cast<__nv_bfloat162*>(dst + off + 2) = __floats2bfloat162_rn(v.z, v.w);
    }
}

// ================= kernel B: featw (bx<40) | contrast (bx>=40) =============
constexpr int LZA = 776;
constexpr int LZB = 776;
constexpr int LSS = 68;
constexpr int B_ZA = 0;
constexpr int B_ZB = 16 * LZA * 2;                 // 24832
constexpr int B_S0 = B_ZB + 64 * LZB * 2;          // 124160
constexpr int B_S1 = B_S0 + 16 * LSS * 4;          // 128512
constexpr int B_SMEM = B_S1 + 16 * LSS * 4;        // 132864

__global__ void __launch_bounds__(256, 1) k_mid() {
    extern __shared__ __align__(16) char dyn[];
    __nv_bfloat16* za = reinterpret_cast<__nv_bfloat16*>(dyn + B_ZA);
    const int tid = threadIdx.x;
    const int w = tid >> 5, lane = tid & 31;

    if (blockIdx.x < 40) {
        const int t = blockIdx.x;
        const bool isA = t < 8;
        const int rbase = (isA ? t : t - 8) * 16;
        const int off = isA ? 0 : ND;

        for (int c = tid; c < 16 * (ND / 8); c += 256) {
            int r = c / (ND / 8), d8 = c % (ND / 8);
            *reinterpret_cast<uint4*>(za + r * LZA + d8 * 8) =
                *reinterpret_cast<const uint4*>(g_zh + (rbase + r) * ND + d8 * 8);
        }
        __syncthreads();

        int h0 = w * 32, h1 = h0 + 16;
        wmma::fragment<wmma::accumulator, 16, 16, 16, float> c0e, c0o, c1e, c1o;
        wmma::fill_fragment(c0e, 0.f); wmma::fill_fragment(c0o, 0.f);
        wmma::fill_fragment(c1e, 0.f); wmma::fill_fragment(c1o, 0.f);
#pragma unroll 4
        for (int kc = 0; kc < ND / 16; kc += 2) {
            wmma::fragment<wmma::matrix_a, 16, 16, 16, __nv_bfloat16, wmma::row_major> ae, ao;
            wmma::fragment<wmma::matrix_b, 16, 16, 16, __nv_bfloat16, wmma::col_major> b0e, b0o, b1e, b1o;
            wmma::load_matrix_sync(ae, za + kc * 16, LZA);
            wmma::load_matrix_sync(ao, za + (kc + 1) * 16, LZA);
            wmma::load_matrix_sync(b0e, g_W1h + h0 * (2 * ND) + off + kc * 16, 2 * ND);
            wmma::load_matrix_sync(b0o, g_W1h + h0 * (2 * ND) + off + (kc + 1) * 16, 2 * ND);
            wmma::load_matrix_sync(b1e, g_W1h + h1 * (2 * ND) + off + kc * 16, 2 * ND);
            wmma::load_matrix_sync(b1o, g_W1h + h1 * (2 * ND) + off + (kc + 1) * 16, 2 * ND);
            wmma::mma_sync(c0e, ae, b0e, c0e);
            wmma::mma_sync(c0o, ao, b0o, c0o);
            wmma::mma_sync(c1e, ae, b1e, c1e);
            wmma::mma_sync(c1o, ao, b1o, c1o);
        }
#pragma unroll
        for (int e = 0; e < c0e.num_elements; e++) { c0e.x[e] += c0o.x[e]; c1e.x[e] += c1o.x[e]; }

        if (isA) {
            float* out = g_A + rbase * NH;
            wmma::store_matrix_sync(out + h0, c0e, NH, wmma::mem_row_major);
            wmma::store_matrix_sync(out + h1, c1e, NH, wmma::mem_row_major);
        } else {
            float* cbuf = reinterpret_cast<float*>(dyn);
            __syncthreads();
            wmma::store_matrix_sync(cbuf + h0, c0e, 260, wmma::mem_row_major);
            wmma::store_matrix_sync(cbuf + h1, c1e, 260, wmma::mem_row_major);
            __syncthreads();
            for (int c = tid; c < 16 * 128; c += 256) {
                int r = c >> 7, p = c & 127;
                __nv_bfloat162 v = __floats2bfloat162_rn(cbuf[r * 260 + 2 * p],
                                                         cbuf[r * 260 + 2 * p + 1]);
                *reinterpret_cast<__nv_bfloat162*>(g_Bfh + (rbase + r) * NH + 2 * p) = v;
            }
        }
    } else {
        const int vb = blockIdx.x - 40;
        const int bx = vb >> 3;
        const int by = vb & 7;
        const int ibase = bx * 16;
        const int kbase = by * 64;

        __nv_bfloat16* zb = reinterpret_cast<__nv_bfloat16*>(dyn + B_ZB);
        float* S0 = reinterpret_cast<float*>(dyn + B_S0);
        float* S1 = reinterpret_cast<float*>(dyn + B_S1);

        for (int c = tid; c < 16 * (ND / 8); c += 256) {
            int r = c / (ND / 8), d8 = c % (ND / 8);
            *reinterpret_cast<uint4*>(za + r * LZA + d8 * 8) =
                *reinterpret_cast<const uint4*>(g_zh + (ibase + r) * ND + d8 * 8);
        }
        for (int c = tid; c < 64 * (ND / 8); c += 256) {
            int r = c / (ND / 8), d8 = c % (ND / 8);
            *reinterpret_cast<uint4*>(zb + r * LZB + d8 * 8) =
                *reinterpret_cast<const uint4*>(g_zh + (kbase + r) * ND + d8 * 8);
        }
        __syncthreads();

        const int wn = w & 3;
        const int wd = w >> 2;
        const int kcol = wn * 16;
        const int d0 = wd * 384;

        wmma::fragment<wmma::accumulator, 16, 16, 16, float> cf0, cf1;
        wmma::fill_fragment(cf0, 0.f);
        wmma::fill_fragment(cf1, 0.f);
#pragma unroll 4
        for (int kc = 0; kc < 24; kc += 2) {
            wmma::fragment<wmma::matrix_a, 16, 16, 16, __nv_bfloat16, wmma::row_major> a0, a1;
            wmma::fragment<wmma::matrix_b, 16, 16, 16, __nv_bfloat16, wmma::col_major> b0, b1;
            wmma::load_matrix_sync(a0, za + d0 + kc * 16, LZA);
            wmma::load_matrix_sync(b0, zb + kcol * LZB + d0 + kc * 16, LZB);
            wmma::load_matrix_sync(a1, za + d0 + (kc + 1) * 16, LZA);
            wmma::load_matrix_sync(b1, zb + kcol * LZB + d0 + (kc + 1) * 16, LZB);
            wmma::mma_sync(cf0, a0, b0, cf0);
            wmma::mma_sync(cf1, a1, b1, cf1);
        }
#pragma unroll
        for (int e = 0; e < cf0.num_elements; e++) cf0.x[e] += cf1.x[e];
        wmma::store_matrix_sync((wd ? S1 : S0) + kcol, cf0, LSS, wmma::mem_row_major);
        __syncthreads();

#pragma unroll
        for (int rr = 2 * w; rr <= 2 * w + 1; rr++) {
            int i = ibase + rr;
            float dacc = 0.f, pacc = 0.f;
#pragma unroll
            for (int cc = 0; cc < 2; cc++) {
                int c = lane + cc * 32;
                int k = kbase + c;
                float s = S0[rr * LSS + c] + S1[rr * LSS + c];
                if (k != i) dacc += expf(TAU_INV * s);
                if (k > i && k < NQ) pacc += s;
            }
#pragma unroll
            for (int o = 16; o; o >>= 1) {
                dacc += __shfl_down_sync(0xffffffffu, dacc, o);
                pacc += __shfl_down_sync(0xffffffffu, pacc, o);
            }
            if (lane == 0) {
                g_denomp[i * 8 + by] = dacc;
                g_pairp[i * 8 + by] = pacc;
            }
        }
    }
}

// ================= kernel C: pair MLP, W2 in regs, i-pairs =================
constexpr int LDH = 264;
constexpr int P_H1A = 0;                           // 128*264*2 = 67584
constexpr int P_H1B = 67584;                       // 67584 -> 135168
constexpr int P_CS = 135168;                       // 8*512*4 = 16384
constexpr int P_PART = P_CS + 16384;               // 2*128*8*4 = 8192
constexpr int P_ASH = P_PART + 8192;               // 4*256*2 = 2048
constexpr int P_B2S = P_ASH + 2048;                // 1024
constexpr int P_W3S = P_B2S + 1024;                // 1024
constexpr int P_RR  = P_W3S + 1024;                // 1024
constexpr int P_SMEM = P_RR + 1024;                // 165888
__global__ void __launch_bounds__(256, 1)
k_pair(const float* __restrict__ b1, const float* __restrict__ b2,
       const float* __restrict__ w3, const float* __restrict__ b3v,
       float* __restrict__ out) {
    extern __shared__ __align__(16) char dyn[];
    __nv_bfloat16* h1a = reinterpret_cast<__nv_bfloat16*>(dyn + P_H1A);
    __nv_bfloat16* h1b = reinterpret_cast<__nv_bfloat16*>(dyn + P_H1B);
    float* cscr = reinterpret_cast<float*>(dyn + P_CS);
    float* part = reinterpret_cast<float*>(dyn + P_PART);   // [2][128*8]
    __nv_bfloat16* ashh = reinterpret_cast<__nv_bfloat16*>(dyn + P_ASH);
    float* b2s = reinterpret_cast<float*>(dyn + P_B2S);
    float* w3s = reinterpret_cast<float*>(dyn + P_W3S);
    float* rr  = reinterpret_cast<float*>(dyn + P_RR);

    const int ibase = blockIdx.x * 4;
    const int j0 = blockIdx.y * 128;
    const int tid = threadIdx.x;
    const int w = tid >> 5, lane = tid & 31;
    const int plocal = lane & 15, half = lane >> 4;
    const int c0 = w * 32;   // this warp's 32 output columns

    {
        int h = tid;
        float bb = b1[h];
#pragma unroll
        for (int ii = 0; ii < 4; ii++)
            ashh[ii * 256 + h] = __float2bfloat16(g_A[(ibase + ii) * NH + h] + bb);
        b2s[h] = b2[h];
        w3s[h] = w3[h];
    }

    // persistent W2 fragments: warp w owns cols [c0, c0+32), all 16 k-steps
    wmma::fragment<wmma::matrix_b, 16, 16, 16, __nv_bfloat16, wmma::col_major> bf0[16], bf1[16];
#pragma unroll
    for (int k = 0; k < 16; k++) {
        wmma::load_matrix_sync(bf0[k], g_W2h + c0 * NH + k * 16, NH);
        wmma::load_matrix_sync(bf1[k], g_W2h + (c0 + 16) * NH + k * 16, NH);
    }

    float* cs = cscr + w * 512;
    const __nv_bfloat162 zero2 = __floats2bfloat162_rn(0.f, 0.f);
    float bacc = 0.f;

    for (int ip = 0; ip < 2; ip++) {
        const int i0 = ibase + 2 * ip, i1 = i0 + 1;
        __syncthreads();   // prev pair h1/part reads done (ash ready on ip==0)

        // fill h1a (i0) and h1b (i1) from ONE Bf load
        const __nv_bfloat16* a0 = ashh + 2 * ip * 256;
        const __nv_bfloat16* a1 = a0 + 256;
        for (int c = tid; c < 128 * 32; c += 256) {
            int j = c >> 5, g = c & 31;
            uint4 bv = *reinterpret_cast<const uint4*>(g_Bfh + (j0 + j) * NH + g * 8);
            const __nv_bfloat162* ap0 = reinterpret_cast<const __nv_bfloat162*>(a0 + g * 8);
            const __nv_bfloat162* ap1 = reinterpret_cast<const __nv_bfloat162*>(a1 + g * 8);
            uint4 va = bv, vb = bv;
            __nv_bfloat162* ha = reinterpret_cast<__nv_bfloat162*>(&va);
            __nv_bfloat162* hb = reinterpret_cast<__nv_bfloat162*>(&vb);
#pragma unroll
            for (int q = 0; q < 4; q++) {
                ha[q] = __hmax2(__hadd2(ha[q], ap0[q]), zero2);
                hb[q] = __hmax2(__hadd2(hb[q], ap1[q]), zero2);
            }
            *reinterpret_cast<uint4*>(h1a + j * LDH + g * 8) = va;
            *reinterpret_cast<uint4*>(h1b + j * LDH + g * 8) = vb;
        }
        __syncthreads();

        // mainloop: 8 M-tiles x 16 k-steps, 4 independent accumulators
        for (int mt = 0; mt < 8; mt++) {
            wmma::fragment<wmma::accumulator, 16, 16, 16, float> acc00, acc01, acc10, acc11;
            wmma::fill_fragment(acc00, 0.f); wmma::fill_fragment(acc01, 0.f);
            wmma::fill_fragment(acc10, 0.f); wmma::fill_fragment(acc11, 0.f);
#pragma unroll
            for (int k = 0; k < 16; k++) {
                wmma::fragment<wmma::matrix_a, 16, 16, 16, __nv_bfloat16, wmma::row_major> afa, afb;
                wmma::load_matrix_sync(afa, h1a + mt * 16 * LDH + k * 16, LDH);
                wmma::load_matrix_sync(afb, h1b + mt * 16 * LDH + k * 16, LDH);
                wmma::mma_sync(acc00, afa, bf0[k], acc00);
                wmma::mma_sync(acc01, afa, bf1[k], acc01);
                wmma::mma_sync(acc10, afb, bf0[k], acc10);
                wmma::mma_sync(acc11, afb, bf1[k], acc11);
            }
            // epilogue pass 1 (i0)
            wmma::store_matrix_sync(cs, acc00, 16, wmma::mem_row_major);
            wmma::store_matrix_sync(cs + 256, acc01, 16, wmma::mem_row_major);
            __syncwarp();
            {
                const float* cp = cs + half * 256 + plocal * 16;
                const int cb = c0 + half * 16;
                float s = 0.f;
#pragma unroll
                for (int q = 0; q < 16; q++)
                    s += fmaxf(cp[q] + b2s[cb + q], 0.f) * w3s[cb + q];
                s += __shfl_down_sync(0xffffffffu, s, 16);
                if (half == 0) part[(mt * 16 + plocal) * 8 + w] = s;
            }
            __syncwarp();
            // epilogue pass 2 (i1)
            wmma::store_matrix_sync(cs, acc10, 16, wmma::mem_row_major);
            wmma::store_matrix_sync(cs + 256, acc11, 16, wmma::mem_row_major);
            __syncwarp();
            {
                const float* cp = cs + half * 256 + plocal * 16;
                const int cb = c0 + half * 16;
                float s = 0.f;
#pragma unroll
                for (int q = 0; q < 16; q++)
                    s += fmaxf(cp[q] + b2s[cb + q], 0.f) * w3s[cb + q];
                s += __shfl_down_sync(0xffffffffu, s, 16);
                if (half == 0) part[1024 + (mt * 16 + plocal) * 8 + w] = s;
            }
            __syncwarp();
        }
        __syncthreads();

        if (tid < 128) {
            int j = j0 + tid;
            float l0 = b3v[0], l1 = l0;
#pragma unroll
            for (int q = 0; q < 8; q++) { l0 += part[tid * 8 + q]; l1 += part[1024 + tid * 8 + q]; }
            if (j > i0) {
                float lab = (j < NM) ? 1.f : 0.f;
                bacc += fmaxf(l0, 0.f) - l0 * lab + log1pf(expf(-fabsf(l0)));
            }
            if (j > i1) {
                float lab = (j < NM) ? 1.f : 0.f;
                bacc += fmaxf(l1, 0.f) - l1 * lab + log1pf(expf(-fabsf(l1)));
            }
        }
    }
    __syncthreads();

    // block reduce bacc
    rr[tid] = bacc;
    __syncthreads();
    for (int st = 128; st > 0; st >>= 1) {
        if (tid < st) rr[tid] += rr[tid + st];
        __syncthreads();
    }
    __shared__ bool isLast;
    if (tid == 0) {
        g_bcep[blockIdx.y * 32 + blockIdx.x] = rr[0];
        __threadfence();
        unsigned v = atomicAdd(&g_ctr, 1u);
        isLast = (v == 127u);
    }
    __syncthreads();
    if (!isLast) return;

    // ----- final reduce (last block, deterministic order) -----
    float b = (tid < 128) ? g_bcep[tid] : 0.f;
    rr[tid] = b;
    __syncthreads();
    for (int st = 128; st > 0; st >>= 1) {
        if (tid < st) rr[tid] += rr[tid + st];
        __syncthreads();
    }
    float bsum = rr[0];
    __syncthreads();

    float c = 0.f;
    if (tid < NQ) {
        int i = tid;
        float den = 0.f, pr = 0.f;
#pragma unroll
        for (int q = 0; q < 8; q++) {
            den += g_denomp[i * 8 + q];
            pr += g_pairp[i * 8 + q];
        }
        c = (float)(NQ - 1 - i) * logf(den) - TAU_INV * pr;
    }
    rr[tid] = c;
    __syncthreads();
    for (int st = 128; st > 0; st >>= 1) {
        if (tid < st) rr[tid] += rr[tid + st];
        __syncthreads();
    }
    if (tid == 0) {
        float closs = (-2.0f * (float)(NQ - 1) / (float)NQ) * rr[0];
        out[0] = closs + bsum / PCOUNT;
    }
}

// ---------------- launch ----------------
extern "C" void kernel_launch(void* const* d_in, const int* in_sizes, int n_in,
                              void* d_out, int out_size) {
    const float* emb = (const float*)d_in[0];
    const float* W1  = (const float*)d_in[1];
    const float* b1  = (const float*)d_in[2];
    const float* W2  = (const float*)d_in[3];
    const float* b2  = (const float*)d_in[4];
    const float* W3  = (const float*)d_in[5];
    const float* b3  = (const float*)d_in[6];

    cudaFuncSetAttribute(k_mid, cudaFuncAttributeMaxDynamicSharedMemorySize, B_SMEM);
    cudaFuncSetAttribute(k_pair, cudaFuncAttributeMaxDynamicSharedMemorySize, P_SMEM);

    k_prep<<<128 + 448, 256>>>(emb, W1, W2);
    k_mid<<<40 + 64, 256, B_SMEM>>>();
    k_pair<<<dim3(32, 4), 256, P_SMEM>>>(b1, b2, W3, b3, (float*)d_out);
}